// round 11
// baseline (speedup 1.0000x reference)
#include <cuda_runtime.h>
#include <cuda_bf16.h>
#include <cstdint>

// dims fixed by setup_inputs
#define NN     2048
#define ABATCH 16
#define DIN    128
#define DOUT   128
#define TCHUNKS 32

// ---------------- device scratch (no allocs allowed) ----------------
__device__ float g_part[TCHUNKS * NN];
__device__ float g_rinv[NN];
__device__ __nv_bfloat16 g_adjT[(size_t)NN * NN];           // adjT[m][n], 8 MB
__device__ __nv_bfloat16 g_yT[(size_t)ABATCH * DOUT * NN];  // yT[ab][d][n], 8 MB
__device__ __nv_bfloat16 g_wt[DOUT * DIN];                  // WT[d][k] bf16

__device__ __forceinline__ uint32_t smem_u32(const void* p) {
    return (uint32_t)__cvta_generic_to_shared(p);
}
__device__ __forceinline__ void cp_async16(uint32_t dst, const void* src) {
    asm volatile("cp.async.cg.shared.global [%0], [%1], 16;" :: "r"(dst), "l"(src));
}
__device__ __forceinline__ void cp_commit() {
    asm volatile("cp.async.commit_group;" ::: "memory");
}
template <int N>
__device__ __forceinline__ void cp_wait() {
    asm volatile("cp.async.wait_group %0;" :: "n"(N) : "memory");
}
__device__ __forceinline__ void ldsm_x4(uint32_t* r, uint32_t addr) {
    asm volatile("ldmatrix.sync.aligned.m8n8.x4.shared.b16 {%0,%1,%2,%3}, [%4];"
                 : "=r"(r[0]), "=r"(r[1]), "=r"(r[2]), "=r"(r[3]) : "r"(addr));
}
__device__ __forceinline__ void mma16816(float* d, const uint32_t* a, const uint32_t* b) {
    asm volatile(
        "mma.sync.aligned.m16n8k16.row.col.f32.bf16.bf16.f32 "
        "{%0,%1,%2,%3}, {%4,%5,%6,%7}, {%8,%9}, {%0,%1,%2,%3};"
        : "+f"(d[0]), "+f"(d[1]), "+f"(d[2]), "+f"(d[3])
        : "r"(a[0]), "r"(a[1]), "r"(a[2]), "r"(a[3]), "r"(b[0]), "r"(b[1]));
}
__device__ __forceinline__ uint32_t pack_bf2(float a, float b) {
    __nv_bfloat162 t = __floats2bfloat162_rn(a, b);
    return *(uint32_t*)&t;
}

// ============================================================
// Kernel 1: fused transpose + partial column sums (64x64 tiles)
// ============================================================
__global__ void __launch_bounds__(256) transpose_colsum_kernel(const float* __restrict__ adj) {
    __shared__ float t[64][65];
    const int mx = blockIdx.x * 64, ny = blockIdx.y * 64;
    const int tid = threadIdx.x;
    const int row = tid >> 2;
    const int q   = tid & 3;

#pragma unroll
    for (int i = 0; i < 4; ++i) {
        const int f4 = q + 4 * i;
        float4 v = *(const float4*)&adj[(size_t)(ny + row) * NN + mx + f4 * 4];
        t[row][f4 * 4 + 0] = v.x;
        t[row][f4 * 4 + 1] = v.y;
        t[row][f4 * 4 + 2] = v.z;
        t[row][f4 * 4 + 3] = v.w;
    }
    __syncthreads();

    const int m  = row;
    const int nq = q * 16;
    float vv[16];
    float s = 0.f;
#pragma unroll
    for (int j = 0; j < 16; ++j) {
        vv[j] = t[nq + j][m];
        s += vv[j];
    }
    uint4 p0, p1;
    p0.x = pack_bf2(vv[0],  vv[1]);  p0.y = pack_bf2(vv[2],  vv[3]);
    p0.z = pack_bf2(vv[4],  vv[5]);  p0.w = pack_bf2(vv[6],  vv[7]);
    p1.x = pack_bf2(vv[8],  vv[9]);  p1.y = pack_bf2(vv[10], vv[11]);
    p1.z = pack_bf2(vv[12], vv[13]); p1.w = pack_bf2(vv[14], vv[15]);
    char* dst = (char*)g_adjT + ((size_t)(mx + m) * NN + ny + nq) * 2;
    *(uint4*)dst        = p0;
    *(uint4*)(dst + 16) = p1;

    s += __shfl_xor_sync(0xFFFFFFFF, s, 1);
    s += __shfl_xor_sync(0xFFFFFFFF, s, 2);
    if (q == 0) g_part[blockIdx.y * NN + mx + m] = s;
}

// ============================================================
// Kernel 2: blocks 0-7: rinv = rsqrt(colsum); blocks 8-15: WT[d][k]=bf16(W[k][d])
// ============================================================
__global__ void rinv_wt_kernel(const float* __restrict__ w) {
    if (blockIdx.x < 8) {
        int col = blockIdx.x * 256 + threadIdx.x;
        float s = 0.f;
#pragma unroll
        for (int c = 0; c < TCHUNKS; ++c)
            s += g_part[c * NN + col];
        g_rinv[col] = rsqrtf(s);
    } else {
        int idx = ((blockIdx.x - 8) * 256 + threadIdx.x) * 8;
        int d  = idx >> 7;
        int k0 = idx & 127;
        uint4 pk;
        float a0 = w[(size_t)(k0 + 0) * DOUT + d], a1 = w[(size_t)(k0 + 1) * DOUT + d];
        float a2 = w[(size_t)(k0 + 2) * DOUT + d], a3 = w[(size_t)(k0 + 3) * DOUT + d];
        float a4 = w[(size_t)(k0 + 4) * DOUT + d], a5 = w[(size_t)(k0 + 5) * DOUT + d];
        float a6 = w[(size_t)(k0 + 6) * DOUT + d], a7 = w[(size_t)(k0 + 7) * DOUT + d];
        pk.x = pack_bf2(a0, a1);
        pk.y = pack_bf2(a2, a3);
        pk.z = pack_bf2(a4, a5);
        pk.w = pack_bf2(a6, a7);
        *(uint4*)((char*)g_wt + (size_t)idx * 2) = pk;
    }
}

// ============================================================
// Kernel 3: fused convert+projection via mma.sync
//   yT[ab][d][n] = bf16( rinv[n] * sum_k WT[d][k] * bf16(x[ab][n][k]) )
// CTA: 128d x 128n, 512 threads, 16 warps (4d x 4n), warp tile 32x32.
// grid (16 n-tiles, 16 ab).
// ============================================================
#define PTILE_B (128 * 128)   // one 64-k chunk tile: 128 rows x 128B = 16 KB

__global__ void __launch_bounds__(512, 1)
project_mma(const float* __restrict__ x) {
    extern __shared__ char smem_raw[];
    const uint32_t sbase = (smem_u32(smem_raw) + 127) & ~127u;
    const uint32_t Ao0 = sbase;                  // WT chunks: 2 x 16KB
    const uint32_t Bo0 = sbase + 2 * PTILE_B;    // x-bf16 chunks: 2 x 16KB

    const int tid  = threadIdx.x;
    const int wid  = tid >> 5;
    const int lane = tid & 31;
    const int warp_m = (wid & 3) * 32;     // d
    const int warp_d = (wid >> 2) * 32;    // n (local)
    const int n0 = blockIdx.x * 128;
    const int ab = blockIdx.y;

    // WT via cp.async into swizzled A tiles
    {
        const char* Ag = (const char*)g_wt;
        const int lrow = tid >> 2;
        const int lc0  = (tid & 3) * 2;
#pragma unroll
        for (int c = 0; c < 2; ++c)
#pragma unroll
            for (int i = 0; i < 2; ++i) {
                int ch = lc0 + i;
                uint32_t sw = (uint32_t)(ch ^ (lrow & 7)) * 16 + (uint32_t)lrow * 128;
                size_t goff = ((size_t)lrow * DIN + c * 64 + ch * 8) * 2;
                cp_async16(Ao0 + c * PTILE_B + sw, Ag + goff);
            }
        cp_commit();
    }

    // x fp32 -> bf16 swizzled B tiles, in registers
    {
        const float* xab = x + ((size_t)ab * NN + n0) * DIN;
        const int f4c = tid & 31;
        const int chunk = f4c >> 4;
        const int ku    = (f4c & 15) >> 1;
        const int half  = f4c & 1;
#pragma unroll
        for (int i = 0; i < 8; ++i) {
            const int row = (tid >> 5) + i * 16;
            float4 v = *(const float4*)&xab[(size_t)row * DIN + f4c * 4];
            uint32_t lo = pack_bf2(v.x, v.y);
            uint32_t hi = pack_bf2(v.z, v.w);
            uint32_t addr = Bo0 + chunk * PTILE_B + (uint32_t)row * 128
                          + (uint32_t)(ku ^ (row & 7)) * 16 + half * 8;
            asm volatile("st.shared.v2.b32 [%0], {%1, %2};" :: "r"(addr), "r"(lo), "r"(hi));
        }
    }
    cp_wait<0>();
    __syncthreads();

    float acc[2][4][4];
#pragma unroll
    for (int mf = 0; mf < 2; ++mf)
#pragma unroll
        for (int nf = 0; nf < 4; ++nf)
#pragma unroll
            for (int e = 0; e < 4; ++e) acc[mf][nf][e] = 0.f;

    const int portion = lane >> 3;
    const int w8 = lane & 7;

#pragma unroll
    for (int c = 0; c < 2; ++c) {
        const uint32_t Ao = Ao0 + c * PTILE_B;
        const uint32_t Bo = Bo0 + c * PTILE_B;
#pragma unroll
        for (int ks = 0; ks < 4; ++ks) {
            const int kb8 = ks * 2;
            uint32_t a[2][4], b[4][2];
#pragma unroll
            for (int mf = 0; mf < 2; ++mf) {
                int row = warp_m + mf * 16 + (portion & 1) * 8 + w8;
                int ch  = kb8 + (portion >> 1);
                ldsm_x4(a[mf], Ao + (uint32_t)row * 128 + (uint32_t)(ch ^ (row & 7)) * 16);
            }
#pragma unroll
            for (int nfp = 0; nfp < 2; ++nfp) {
                int row = warp_d + nfp * 16 + (portion >> 1) * 8 + w8;
                int ch  = kb8 + (portion & 1);
                uint32_t r[4];
                ldsm_x4(r, Bo + (uint32_t)row * 128 + (uint32_t)(ch ^ (row & 7)) * 16);
                b[2 * nfp][0]     = r[0];
                b[2 * nfp][1]     = r[1];
                b[2 * nfp + 1][0] = r[2];
                b[2 * nfp + 1][1] = r[3];
            }
#pragma unroll
            for (int mf = 0; mf < 2; ++mf)
#pragma unroll
                for (int nf = 0; nf < 4; ++nf)
                    mma16816(acc[mf][nf], a[mf], b[nf]);
        }
    }

    const int g  = lane >> 2;
    const int tc = lane & 3;
    char* yT = (char*)(g_yT + (size_t)ab * DOUT * NN);
#pragma unroll
    for (int mf = 0; mf < 2; ++mf) {
        const int d0g = warp_m + mf * 16 + g;
#pragma unroll
        for (int nf = 0; nf < 4; ++nf) {
            const int ng = n0 + warp_d + nf * 8 + tc * 2;
            const float rv0 = g_rinv[ng];
            const float rv1 = g_rinv[ng + 1];
            *(uint32_t*)(yT + ((size_t)d0g * NN + ng) * 2) =
                pack_bf2(acc[mf][nf][0] * rv0, acc[mf][nf][1] * rv1);
            *(uint32_t*)(yT + ((size_t)(d0g + 8) * NN + ng) * 2) =
                pack_bf2(acc[mf][nf][2] * rv0, acc[mf][nf][3] * rv1);
        }
    }
}

// ============================================================
// Kernel 4: mma.sync bf16 aggregate (v5: 64m x 128d CTAs, 2 CTAs/SM)
//   out[ab][m][d] = relu( rinv[m] * sum_n adjT[m][n]*yT[ab][d][n] + bias[d] )
// 256 threads, 8 warps (2m x 4d), warp 32x32. BK=128 chunk:
// A = 2 sub-tiles 64x64 (8KB), B = 2 sub-tiles 128x64 (16KB). Stage=48KB,
// double-buffered = 96KB -> 2 CTAs/SM. grid (32 m-tiles, 16 ab).
// ============================================================
#define A_SUB_B   (64 * 128)           // 8 KB
#define B_SUB_B   (128 * 128)          // 16 KB
#define STAGE_B   (2 * A_SUB_B + 2 * B_SUB_B)   // 48 KB
#define NCHUNKS   16                   // 2048 / 128

__global__ void __launch_bounds__(256, 2)
aggregate_mma(const float* __restrict__ bias, float* __restrict__ out) {
    extern __shared__ char smem_raw[];
    const uint32_t sbase = (smem_u32(smem_raw) + 127) & ~127u;

    const int tid  = threadIdx.x;
    const int wid  = tid >> 5;
    const int lane = tid & 31;
    const int warp_m = (wid & 1) * 32;     // 0,32 (m within 64)
    const int warp_d = (wid >> 1) * 32;    // 0,32,64,96 (d)
    const int m0   = blockIdx.x * 64;
    const int ab   = blockIdx.y;

    const char* Ag = (const char*)(g_adjT + (size_t)m0 * NN);
    const char* Bg = (const char*)(g_yT + (size_t)ab * DOUT * NN);

    // loader: A: r=tid>>2 (0..63), 2 f4/sub; B: r=tid>>1 (0..127), 4 f4/sub
    const int ar  = tid >> 2;
    const int aq  = (tid & 3) * 2;
    const int br  = tid >> 1;
    const int bq  = (tid & 1) * 4;

    auto load_buf = [&](int buf, int c) {
        const uint32_t Ao = sbase + buf * STAGE_B;
        const uint32_t Bo = Ao + 2 * A_SUB_B;
        const size_t An = (size_t)ar * NN + (size_t)c * 128;
        const size_t Bn = (size_t)br * NN + (size_t)c * 128;
#pragma unroll
        for (int s = 0; s < 2; ++s) {
#pragma unroll
            for (int i = 0; i < 2; ++i) {
                int ch = aq + i;
                uint32_t sw = (uint32_t)(ch ^ (ar & 7)) * 16 + (uint32_t)ar * 128;
                cp_async16(Ao + s * A_SUB_B + sw, Ag + (An + s * 64 + ch * 8) * 2);
            }
#pragma unroll
            for (int i = 0; i < 4; ++i) {
                int ch = bq + i;
                uint32_t sw = (uint32_t)(ch ^ (br & 7)) * 16 + (uint32_t)br * 128;
                cp_async16(Bo + s * B_SUB_B + sw, Bg + (Bn + s * 64 + ch * 8) * 2);
            }
        }
        cp_commit();
    };

    float acc[2][4][4];
#pragma unroll
    for (int mf = 0; mf < 2; ++mf)
#pragma unroll
        for (int nf = 0; nf < 4; ++nf)
#pragma unroll
            for (int e = 0; e < 4; ++e) acc[mf][nf][e] = 0.f;

    load_buf(0, 0);

    const int portion = lane >> 3;
    const int w8 = lane & 7;

    uint32_t afr[2][2][4], bfr[2][4][2];

    for (int c = 0; c < NCHUNKS; ++c) {
        const int buf = c & 1;
        if (c + 1 < NCHUNKS) {
            load_buf(buf ^ 1, c + 1);
            cp_wait<1>();
        } else {
            cp_wait<0>();
        }
        __syncthreads();

        const uint32_t Ao = sbase + buf * STAGE_B;
        const uint32_t Bo = Ao + 2 * A_SUB_B;

        auto ldfrag = [&](int ks, uint32_t (&a)[2][4], uint32_t (&b)[4][2]) {
            const int sub = ks >> 2;
            const int kb8 = (ks & 3) * 2;
            const uint32_t As = Ao + sub * A_SUB_B;
            const uint32_t Bs = Bo + sub * B_SUB_B;
#pragma unroll
            for (int mf = 0; mf < 2; ++mf) {
                int row = warp_m + mf * 16 + (portion & 1) * 8 + w8;
                int ch  = kb8 + (portion >> 1);
                ldsm_x4(a[mf], As + (uint32_t)row * 128 + (uint32_t)(ch ^ (row & 7)) * 16);
            }
#pragma unroll
            for (int nfp = 0; nfp < 2; ++nfp) {
                int row = warp_d + nfp * 16 + (portion >> 1) * 8 + w8;
                int ch  = kb8 + (portion & 1);
                uint32_t r[4];
                ldsm_x4(r, Bs + (uint32_t)row * 128 + (uint32_t)(ch ^ (row & 7)) * 16);
                b[2 * nfp][0]     = r[0];
                b[2 * nfp][1]     = r[1];
                b[2 * nfp + 1][0] = r[2];
                b[2 * nfp + 1][1] = r[3];
            }
        };

        ldfrag(0, afr[0], bfr[0]);
#pragma unroll
        for (int ks = 0; ks < 8; ++ks) {
            const int cur = ks & 1;
            if (ks < 7) ldfrag(ks + 1, afr[cur ^ 1], bfr[cur ^ 1]);
#pragma unroll
            for (int mf = 0; mf < 2; ++mf)
#pragma unroll
                for (int nf = 0; nf < 4; ++nf)
                    mma16816(acc[mf][nf], afr[cur][mf], bfr[cur][nf]);
        }
        __syncthreads();
    }

    const int g  = lane >> 2;
    const int tc = lane & 3;
    float* outab = out + (size_t)ab * NN * DOUT;
#pragma unroll
    for (int mf = 0; mf < 2; ++mf) {
        const int mrow0 = m0 + warp_m + mf * 16 + g;
        const float rv0 = g_rinv[mrow0];
        const float rv1 = g_rinv[mrow0 + 8];
#pragma unroll
        for (int nf = 0; nf < 4; ++nf) {
            const int d0 = warp_d + nf * 8 + tc * 2;
            const float b0 = __ldg(&bias[d0]);
            const float b1 = __ldg(&bias[d0 + 1]);
            float2 v0, v1;
            v0.x = fmaxf(fmaf(acc[mf][nf][0], rv0, b0), 0.f);
            v0.y = fmaxf(fmaf(acc[mf][nf][1], rv0, b1), 0.f);
            v1.x = fmaxf(fmaf(acc[mf][nf][2], rv1, b0), 0.f);
            v1.y = fmaxf(fmaf(acc[mf][nf][3], rv1, b1), 0.f);
            *(float2*)&outab[(size_t)mrow0 * DOUT + d0]       = v0;
            *(float2*)&outab[(size_t)(mrow0 + 8) * DOUT + d0] = v1;
        }
    }
}

// ============================================================
extern "C" void kernel_launch(void* const* d_in, const int* in_sizes, int n_in,
                              void* d_out, int out_size) {
    const float* adj  = (const float*)d_in[0];
    const float* x    = (const float*)d_in[1];
    const float* w    = (const float*)d_in[2];
    const float* bias = (const float*)d_in[3];
    float* out        = (float*)d_out;

    const int agg_smem  = 2 * STAGE_B + 256;   // 96 KB + slack
    const int proj_smem = 4 * PTILE_B + 256;   // 64 KB + slack
    cudaFuncSetAttribute(aggregate_mma, cudaFuncAttributeMaxDynamicSharedMemorySize, agg_smem);
    cudaFuncSetAttribute(project_mma, cudaFuncAttributeMaxDynamicSharedMemorySize, proj_smem);

    transpose_colsum_kernel<<<dim3(32, 32), 256>>>(adj);
    rinv_wt_kernel<<<16, 256>>>(w);
    project_mma<<<dim3(16, 16), 512, proj_smem>>>(x);
    aggregate_mma<<<dim3(32, 16), 256, agg_smem>>>(bias, out);
}

// round 12
// speedup vs baseline: 1.1632x; 1.1632x over previous
#include <cuda_runtime.h>
#include <cuda_bf16.h>
#include <cstdint>

// dims fixed by setup_inputs
#define NN     2048
#define ABATCH 16
#define DIN    128
#define DOUT   128
#define TCHUNKS 32

// ---------------- device scratch (no allocs allowed) ----------------
__device__ float g_part[TCHUNKS * NN];
__device__ float g_rinv[NN];
__device__ __nv_bfloat16 g_adjT[(size_t)NN * NN];           // adjT[m][n], 8 MB
__device__ __nv_bfloat16 g_yT[(size_t)ABATCH * DOUT * NN];  // yT[ab][d][n], 8 MB
__device__ __nv_bfloat16 g_wt[DOUT * DIN];                  // WT[d][k] bf16

__device__ __forceinline__ uint32_t smem_u32(const void* p) {
    return (uint32_t)__cvta_generic_to_shared(p);
}
__device__ __forceinline__ void cp_async16(uint32_t dst, const void* src) {
    asm volatile("cp.async.cg.shared.global [%0], [%1], 16;" :: "r"(dst), "l"(src));
}
__device__ __forceinline__ void cp_commit() {
    asm volatile("cp.async.commit_group;" ::: "memory");
}
template <int N>
__device__ __forceinline__ void cp_wait() {
    asm volatile("cp.async.wait_group %0;" :: "n"(N) : "memory");
}
__device__ __forceinline__ void ldsm_x4(uint32_t* r, uint32_t addr) {
    asm volatile("ldmatrix.sync.aligned.m8n8.x4.shared.b16 {%0,%1,%2,%3}, [%4];"
                 : "=r"(r[0]), "=r"(r[1]), "=r"(r[2]), "=r"(r[3]) : "r"(addr));
}
__device__ __forceinline__ void mma16816(float* d, const uint32_t* a, const uint32_t* b) {
    asm volatile(
        "mma.sync.aligned.m16n8k16.row.col.f32.bf16.bf16.f32 "
        "{%0,%1,%2,%3}, {%4,%5,%6,%7}, {%8,%9}, {%0,%1,%2,%3};"
        : "+f"(d[0]), "+f"(d[1]), "+f"(d[2]), "+f"(d[3])
        : "r"(a[0]), "r"(a[1]), "r"(a[2]), "r"(a[3]), "r"(b[0]), "r"(b[1]));
}
__device__ __forceinline__ uint32_t pack_bf2(float a, float b) {
    __nv_bfloat162 t = __floats2bfloat162_rn(a, b);
    return *(uint32_t*)&t;
}

// ============================================================
// Kernel 1: fused transpose + partial column sums (64x64 tiles)
// ============================================================
__global__ void __launch_bounds__(256) transpose_colsum_kernel(const float* __restrict__ adj) {
    __shared__ float t[64][65];
    const int mx = blockIdx.x * 64, ny = blockIdx.y * 64;
    const int tid = threadIdx.x;
    const int row = tid >> 2;
    const int q   = tid & 3;

#pragma unroll
    for (int i = 0; i < 4; ++i) {
        const int f4 = q + 4 * i;
        float4 v = *(const float4*)&adj[(size_t)(ny + row) * NN + mx + f4 * 4];
        t[row][f4 * 4 + 0] = v.x;
        t[row][f4 * 4 + 1] = v.y;
        t[row][f4 * 4 + 2] = v.z;
        t[row][f4 * 4 + 3] = v.w;
    }
    __syncthreads();

    const int m  = row;
    const int nq = q * 16;
    float vv[16];
    float s = 0.f;
#pragma unroll
    for (int j = 0; j < 16; ++j) {
        vv[j] = t[nq + j][m];
        s += vv[j];
    }
    uint4 p0, p1;
    p0.x = pack_bf2(vv[0],  vv[1]);  p0.y = pack_bf2(vv[2],  vv[3]);
    p0.z = pack_bf2(vv[4],  vv[5]);  p0.w = pack_bf2(vv[6],  vv[7]);
    p1.x = pack_bf2(vv[8],  vv[9]);  p1.y = pack_bf2(vv[10], vv[11]);
    p1.z = pack_bf2(vv[12], vv[13]); p1.w = pack_bf2(vv[14], vv[15]);
    char* dst = (char*)g_adjT + ((size_t)(mx + m) * NN + ny + nq) * 2;
    *(uint4*)dst        = p0;
    *(uint4*)(dst + 16) = p1;

    s += __shfl_xor_sync(0xFFFFFFFF, s, 1);
    s += __shfl_xor_sync(0xFFFFFFFF, s, 2);
    if (q == 0) g_part[blockIdx.y * NN + mx + m] = s;
}

// ============================================================
// Kernel 2: blocks 0-7: rinv = rsqrt(colsum); blocks 8-15: WT[d][k]=bf16(W[k][d])
// ============================================================
__global__ void rinv_wt_kernel(const float* __restrict__ w) {
    if (blockIdx.x < 8) {
        int col = blockIdx.x * 256 + threadIdx.x;
        float s = 0.f;
#pragma unroll
        for (int c = 0; c < TCHUNKS; ++c)
            s += g_part[c * NN + col];
        g_rinv[col] = rsqrtf(s);
    } else {
        int idx = ((blockIdx.x - 8) * 256 + threadIdx.x) * 8;
        int d  = idx >> 7;
        int k0 = idx & 127;
        uint4 pk;
        float a0 = w[(size_t)(k0 + 0) * DOUT + d], a1 = w[(size_t)(k0 + 1) * DOUT + d];
        float a2 = w[(size_t)(k0 + 2) * DOUT + d], a3 = w[(size_t)(k0 + 3) * DOUT + d];
        float a4 = w[(size_t)(k0 + 4) * DOUT + d], a5 = w[(size_t)(k0 + 5) * DOUT + d];
        float a6 = w[(size_t)(k0 + 6) * DOUT + d], a7 = w[(size_t)(k0 + 7) * DOUT + d];
        pk.x = pack_bf2(a0, a1);
        pk.y = pack_bf2(a2, a3);
        pk.z = pack_bf2(a4, a5);
        pk.w = pack_bf2(a6, a7);
        *(uint4*)((char*)g_wt + (size_t)idx * 2) = pk;
    }
}

// ============================================================
// Kernel 3: fused convert+projection via mma.sync
//   yT[ab][d][n] = bf16( rinv[n] * sum_k WT[d][k] * bf16(x[ab][n][k]) )
// CTA: 128d x 128n, 512 threads, 16 warps (4d x 4n), warp tile 32x32.
// grid (16 n-tiles, 16 ab).
// ============================================================
#define PTILE_B (128 * 128)   // one 64-k chunk tile: 128 rows x 128B = 16 KB

__global__ void __launch_bounds__(512, 1)
project_mma(const float* __restrict__ x) {
    extern __shared__ char smem_raw[];
    const uint32_t sbase = (smem_u32(smem_raw) + 127) & ~127u;
    const uint32_t Ao0 = sbase;                  // WT chunks: 2 x 16KB
    const uint32_t Bo0 = sbase + 2 * PTILE_B;    // x-bf16 chunks: 2 x 16KB

    const int tid  = threadIdx.x;
    const int wid  = tid >> 5;
    const int lane = tid & 31;
    const int warp_m = (wid & 3) * 32;     // d
    const int warp_d = (wid >> 2) * 32;    // n (local)
    const int n0 = blockIdx.x * 128;
    const int ab = blockIdx.y;

    // WT via cp.async into swizzled A tiles
    {
        const char* Ag = (const char*)g_wt;
        const int lrow = tid >> 2;
        const int lc0  = (tid & 3) * 2;
#pragma unroll
        for (int c = 0; c < 2; ++c)
#pragma unroll
            for (int i = 0; i < 2; ++i) {
                int ch = lc0 + i;
                uint32_t sw = (uint32_t)(ch ^ (lrow & 7)) * 16 + (uint32_t)lrow * 128;
                size_t goff = ((size_t)lrow * DIN + c * 64 + ch * 8) * 2;
                cp_async16(Ao0 + c * PTILE_B + sw, Ag + goff);
            }
        cp_commit();
    }

    // x fp32 -> bf16 swizzled B tiles, in registers
    {
        const float* xab = x + ((size_t)ab * NN + n0) * DIN;
        const int f4c = tid & 31;
        const int chunk = f4c >> 4;
        const int ku    = (f4c & 15) >> 1;
        const int half  = f4c & 1;
#pragma unroll
        for (int i = 0; i < 8; ++i) {
            const int row = (tid >> 5) + i * 16;
            float4 v = *(const float4*)&xab[(size_t)row * DIN + f4c * 4];
            uint32_t lo = pack_bf2(v.x, v.y);
            uint32_t hi = pack_bf2(v.z, v.w);
            uint32_t addr = Bo0 + chunk * PTILE_B + (uint32_t)row * 128
                          + (uint32_t)(ku ^ (row & 7)) * 16 + half * 8;
            asm volatile("st.shared.v2.b32 [%0], {%1, %2};" :: "r"(addr), "r"(lo), "r"(hi));
        }
    }
    cp_wait<0>();
    __syncthreads();

    float acc[2][4][4];
#pragma unroll
    for (int mf = 0; mf < 2; ++mf)
#pragma unroll
        for (int nf = 0; nf < 4; ++nf)
#pragma unroll
            for (int e = 0; e < 4; ++e) acc[mf][nf][e] = 0.f;

    const int portion = lane >> 3;
    const int w8 = lane & 7;

#pragma unroll
    for (int c = 0; c < 2; ++c) {
        const uint32_t Ao = Ao0 + c * PTILE_B;
        const uint32_t Bo = Bo0 + c * PTILE_B;
#pragma unroll
        for (int ks = 0; ks < 4; ++ks) {
            const int kb8 = ks * 2;
            uint32_t a[2][4], b[4][2];
#pragma unroll
            for (int mf = 0; mf < 2; ++mf) {
                int row = warp_m + mf * 16 + (portion & 1) * 8 + w8;
                int ch  = kb8 + (portion >> 1);
                ldsm_x4(a[mf], Ao + (uint32_t)row * 128 + (uint32_t)(ch ^ (row & 7)) * 16);
            }
#pragma unroll
            for (int nfp = 0; nfp < 2; ++nfp) {
                int row = warp_d + nfp * 16 + (portion >> 1) * 8 + w8;
                int ch  = kb8 + (portion & 1);
                uint32_t r[4];
                ldsm_x4(r, Bo + (uint32_t)row * 128 + (uint32_t)(ch ^ (row & 7)) * 16);
                b[2 * nfp][0]     = r[0];
                b[2 * nfp][1]     = r[1];
                b[2 * nfp + 1][0] = r[2];
                b[2 * nfp + 1][1] = r[3];
            }
#pragma unroll
            for (int mf = 0; mf < 2; ++mf)
#pragma unroll
                for (int nf = 0; nf < 4; ++nf)
                    mma16816(acc[mf][nf], a[mf], b[nf]);
        }
    }

    const int g  = lane >> 2;
    const int tc = lane & 3;
    char* yT = (char*)(g_yT + (size_t)ab * DOUT * NN);
#pragma unroll
    for (int mf = 0; mf < 2; ++mf) {
        const int d0g = warp_m + mf * 16 + g;
#pragma unroll
        for (int nf = 0; nf < 4; ++nf) {
            const int ng = n0 + warp_d + nf * 8 + tc * 2;
            const float rv0 = g_rinv[ng];
            const float rv1 = g_rinv[ng + 1];
            *(uint32_t*)(yT + ((size_t)d0g * NN + ng) * 2) =
                pack_bf2(acc[mf][nf][0] * rv0, acc[mf][nf][1] * rv1);
            *(uint32_t*)(yT + ((size_t)(d0g + 8) * NN + ng) * 2) =
                pack_bf2(acc[mf][nf][2] * rv0, acc[mf][nf][3] * rv1);
        }
    }
}

// ============================================================
// Kernel 4: mma.sync bf16 aggregate (v6: 256m x 128d CTA, single wave)
//   out[ab][m][d] = relu( rinv[m] * sum_n adjT[m][n]*yT[ab][d][n] + bias[d] )
// 512 threads, 16 warps (4m x 4d), warp tile 64m x 32d. BK=64.
// A tile 256x64 (32KB), B tile 128x64 (16KB), 3 stages (144KB).
// grid (8 m-tiles, 16 ab) = 128 CTAs = one wave.
// ============================================================
#define A_TILE_B  (256 * 128)          // 32 KB
#define B_TILE_B  (128 * 128)          // 16 KB
#define STAGE_B   (A_TILE_B + B_TILE_B) // 48 KB
#define NSTAGES   3
#define NCHUNKS   32                   // 2048 / 64

__global__ void __launch_bounds__(512, 1)
aggregate_mma(const float* __restrict__ bias, float* __restrict__ out) {
    extern __shared__ char smem_raw[];
    const uint32_t sbase = (smem_u32(smem_raw) + 127) & ~127u;

    const int tid  = threadIdx.x;
    const int wid  = tid >> 5;
    const int lane = tid & 31;
    const int warp_m = (wid & 3) * 64;     // 0,64,128,192
    const int warp_d = (wid >> 2) * 32;    // 0,32,64,96
    const int m0   = blockIdx.x * 256;
    const int ab   = blockIdx.y;

    const char* Ag = (const char*)(g_adjT + (size_t)m0 * NN);
    const char* Bg = (const char*)(g_yT + (size_t)ab * DOUT * NN);

    // loader: A: 256 rows x 8 f4 = 2048 f4 -> 4/thread; B: 128 x 8 = 1024 -> 2/thread
    const int arow = tid >> 1;            // 0..255
    const int aq   = (tid & 1) * 4;       // 0 or 4
    const int brow = tid >> 2;            // 0..127
    const int bq   = (tid & 3) * 2;       // 0,2,4,6

    auto load_buf = [&](int buf, int c) {
        const uint32_t Ao = sbase + buf * STAGE_B;
        const uint32_t Bo = Ao + A_TILE_B;
        const size_t An = (size_t)arow * NN + (size_t)c * 64;
        const size_t Bn = (size_t)brow * NN + (size_t)c * 64;
#pragma unroll
        for (int i = 0; i < 4; ++i) {
            int ch = aq + i;
            uint32_t sw = (uint32_t)(ch ^ (arow & 7)) * 16 + (uint32_t)arow * 128;
            cp_async16(Ao + sw, Ag + (An + ch * 8) * 2);
        }
#pragma unroll
        for (int i = 0; i < 2; ++i) {
            int ch = bq + i;
            uint32_t sw = (uint32_t)(ch ^ (brow & 7)) * 16 + (uint32_t)brow * 128;
            cp_async16(Bo + sw, Bg + (Bn + ch * 8) * 2);
        }
        cp_commit();
    };

    float acc[4][4][4];
#pragma unroll
    for (int mf = 0; mf < 4; ++mf)
#pragma unroll
        for (int nf = 0; nf < 4; ++nf)
#pragma unroll
            for (int e = 0; e < 4; ++e) acc[mf][nf][e] = 0.f;

    load_buf(0, 0);
    load_buf(1, 1);

    const int portion = lane >> 3;
    const int w8 = lane & 7;

    for (int c = 0; c < NCHUNKS; ++c) {
        if (c + 1 < NCHUNKS) cp_wait<1>(); else cp_wait<0>();
        __syncthreads();
        if (c + 2 < NCHUNKS) load_buf((c + 2) % NSTAGES, c + 2);

        const uint32_t Ao = sbase + (c % NSTAGES) * STAGE_B;
        const uint32_t Bo = Ao + A_TILE_B;

#pragma unroll
        for (int ks = 0; ks < 4; ++ks) {
            const int kb8 = ks * 2;
            uint32_t a[4][4], b[4][2];
#pragma unroll
            for (int mf = 0; mf < 4; ++mf) {
                int row = warp_m + mf * 16 + (portion & 1) * 8 + w8;
                int ch  = kb8 + (portion >> 1);
                ldsm_x4(a[mf], Ao + (uint32_t)row * 128 + (uint32_t)(ch ^ (row & 7)) * 16);
            }
#pragma unroll
            for (int nfp = 0; nfp < 2; ++nfp) {
                int row = warp_d + nfp * 16 + (portion >> 1) * 8 + w8;
                int ch  = kb8 + (portion & 1);
                uint32_t r[4];
                ldsm_x4(r, Bo + (uint32_t)row * 128 + (uint32_t)(ch ^ (row & 7)) * 16);
                b[2 * nfp][0]     = r[0];
                b[2 * nfp][1]     = r[1];
                b[2 * nfp + 1][0] = r[2];
                b[2 * nfp + 1][1] = r[3];
            }
#pragma unroll
            for (int mf = 0; mf < 4; ++mf)
#pragma unroll
                for (int nf = 0; nf < 4; ++nf)
                    mma16816(acc[mf][nf], a[mf], b[nf]);
        }
        __syncthreads();
    }

    const int g  = lane >> 2;
    const int tc = lane & 3;
    float* outab = out + (size_t)ab * NN * DOUT;
#pragma unroll
    for (int mf = 0; mf < 4; ++mf) {
        const int mrow0 = m0 + warp_m + mf * 16 + g;
        const float rv0 = g_rinv[mrow0];
        const float rv1 = g_rinv[mrow0 + 8];
#pragma unroll
        for (int nf = 0; nf < 4; ++nf) {
            const int d0 = warp_d + nf * 8 + tc * 2;
            const float b0 = __ldg(&bias[d0]);
            const float b1 = __ldg(&bias[d0 + 1]);
            float2 v0, v1;
            v0.x = fmaxf(fmaf(acc[mf][nf][0], rv0, b0), 0.f);
            v0.y = fmaxf(fmaf(acc[mf][nf][1], rv0, b1), 0.f);
            v1.x = fmaxf(fmaf(acc[mf][nf][2], rv1, b0), 0.f);
            v1.y = fmaxf(fmaf(acc[mf][nf][3], rv1, b1), 0.f);
            *(float2*)&outab[(size_t)mrow0 * DOUT + d0]       = v0;
            *(float2*)&outab[(size_t)(mrow0 + 8) * DOUT + d0] = v1;
        }
    }
}

// ============================================================
extern "C" void kernel_launch(void* const* d_in, const int* in_sizes, int n_in,
                              void* d_out, int out_size) {
    const float* adj  = (const float*)d_in[0];
    const float* x    = (const float*)d_in[1];
    const float* w    = (const float*)d_in[2];
    const float* bias = (const float*)d_in[3];
    float* out        = (float*)d_out;

    const int agg_smem  = NSTAGES * STAGE_B + 256;   // 144 KB + slack
    const int proj_smem = 4 * PTILE_B + 256;         // 64 KB + slack
    cudaFuncSetAttribute(aggregate_mma, cudaFuncAttributeMaxDynamicSharedMemorySize, agg_smem);
    cudaFuncSetAttribute(project_mma, cudaFuncAttributeMaxDynamicSharedMemorySize, proj_smem);

    transpose_colsum_kernel<<<dim3(32, 32), 256>>>(adj);
    rinv_wt_kernel<<<16, 256>>>(w);
    project_mma<<<dim3(16, 16), 512, proj_smem>>>(x);
    aggregate_mma<<<dim3(8, 16), 512, agg_smem>>>(bias, out);
}

// round 13
// speedup vs baseline: 1.1847x; 1.0185x over previous
#include <cuda_runtime.h>
#include <cuda_bf16.h>
#include <cstdint>

// dims fixed by setup_inputs
#define NN     2048
#define ABATCH 16
#define DIN    128
#define DOUT   128
#define TCHUNKS 32

// ---------------- device scratch (no allocs allowed) ----------------
__device__ float g_part[TCHUNKS * NN];
__device__ float g_rinv[NN];
__device__ __nv_bfloat16 g_adjT[(size_t)NN * NN];           // adjT[m][n], 8 MB
__device__ __nv_bfloat16 g_yT[(size_t)ABATCH * DOUT * NN];  // yT[ab][d][n], 8 MB
__device__ __nv_bfloat16 g_wt[DOUT * DIN];                  // WT[d][k] bf16

__device__ __forceinline__ uint32_t smem_u32(const void* p) {
    return (uint32_t)__cvta_generic_to_shared(p);
}
__device__ __forceinline__ void cp_async16(uint32_t dst, const void* src) {
    asm volatile("cp.async.cg.shared.global [%0], [%1], 16;" :: "r"(dst), "l"(src));
}
__device__ __forceinline__ void cp_commit() {
    asm volatile("cp.async.commit_group;" ::: "memory");
}
template <int N>
__device__ __forceinline__ void cp_wait() {
    asm volatile("cp.async.wait_group %0;" :: "n"(N) : "memory");
}
__device__ __forceinline__ void ldsm_x4(uint32_t* r, uint32_t addr) {
    asm volatile("ldmatrix.sync.aligned.m8n8.x4.shared.b16 {%0,%1,%2,%3}, [%4];"
                 : "=r"(r[0]), "=r"(r[1]), "=r"(r[2]), "=r"(r[3]) : "r"(addr));
}
__device__ __forceinline__ void mma16816(float* d, const uint32_t* a, const uint32_t* b) {
    asm volatile(
        "mma.sync.aligned.m16n8k16.row.col.f32.bf16.bf16.f32 "
        "{%0,%1,%2,%3}, {%4,%5,%6,%7}, {%8,%9}, {%0,%1,%2,%3};"
        : "+f"(d[0]), "+f"(d[1]), "+f"(d[2]), "+f"(d[3])
        : "r"(a[0]), "r"(a[1]), "r"(a[2]), "r"(a[3]), "r"(b[0]), "r"(b[1]));
}
__device__ __forceinline__ uint32_t pack_bf2(float a, float b) {
    __nv_bfloat162 t = __floats2bfloat162_rn(a, b);
    return *(uint32_t*)&t;
}

// ============================================================
// Kernel 1: fused transpose + partial column sums (64x64 tiles)
// ============================================================
__global__ void __launch_bounds__(256) transpose_colsum_kernel(const float* __restrict__ adj) {
    __shared__ float t[64][65];
    const int mx = blockIdx.x * 64, ny = blockIdx.y * 64;
    const int tid = threadIdx.x;
    const int row = tid >> 2;
    const int q   = tid & 3;

#pragma unroll
    for (int i = 0; i < 4; ++i) {
        const int f4 = q + 4 * i;
        float4 v = *(const float4*)&adj[(size_t)(ny + row) * NN + mx + f4 * 4];
        t[row][f4 * 4 + 0] = v.x;
        t[row][f4 * 4 + 1] = v.y;
        t[row][f4 * 4 + 2] = v.z;
        t[row][f4 * 4 + 3] = v.w;
    }
    __syncthreads();

    const int m  = row;
    const int nq = q * 16;
    float vv[16];
    float s = 0.f;
#pragma unroll
    for (int j = 0; j < 16; ++j) {
        vv[j] = t[nq + j][m];
        s += vv[j];
    }
    uint4 p0, p1;
    p0.x = pack_bf2(vv[0],  vv[1]);  p0.y = pack_bf2(vv[2],  vv[3]);
    p0.z = pack_bf2(vv[4],  vv[5]);  p0.w = pack_bf2(vv[6],  vv[7]);
    p1.x = pack_bf2(vv[8],  vv[9]);  p1.y = pack_bf2(vv[10], vv[11]);
    p1.z = pack_bf2(vv[12], vv[13]); p1.w = pack_bf2(vv[14], vv[15]);
    char* dst = (char*)g_adjT + ((size_t)(mx + m) * NN + ny + nq) * 2;
    *(uint4*)dst        = p0;
    *(uint4*)(dst + 16) = p1;

    s += __shfl_xor_sync(0xFFFFFFFF, s, 1);
    s += __shfl_xor_sync(0xFFFFFFFF, s, 2);
    if (q == 0) g_part[blockIdx.y * NN + mx + m] = s;
}

// ============================================================
// Kernel 2: blocks 0-7: rinv = rsqrt(colsum); blocks 8-15: WT[d][k]=bf16(W[k][d])
// ============================================================
__global__ void rinv_wt_kernel(const float* __restrict__ w) {
    if (blockIdx.x < 8) {
        int col = blockIdx.x * 256 + threadIdx.x;
        float s = 0.f;
#pragma unroll
        for (int c = 0; c < TCHUNKS; ++c)
            s += g_part[c * NN + col];
        g_rinv[col] = rsqrtf(s);
    } else {
        int idx = ((blockIdx.x - 8) * 256 + threadIdx.x) * 8;
        int d  = idx >> 7;
        int k0 = idx & 127;
        uint4 pk;
        float a0 = w[(size_t)(k0 + 0) * DOUT + d], a1 = w[(size_t)(k0 + 1) * DOUT + d];
        float a2 = w[(size_t)(k0 + 2) * DOUT + d], a3 = w[(size_t)(k0 + 3) * DOUT + d];
        float a4 = w[(size_t)(k0 + 4) * DOUT + d], a5 = w[(size_t)(k0 + 5) * DOUT + d];
        float a6 = w[(size_t)(k0 + 6) * DOUT + d], a7 = w[(size_t)(k0 + 7) * DOUT + d];
        pk.x = pack_bf2(a0, a1);
        pk.y = pack_bf2(a2, a3);
        pk.z = pack_bf2(a4, a5);
        pk.w = pack_bf2(a6, a7);
        *(uint4*)((char*)g_wt + (size_t)idx * 2) = pk;
    }
}

// ============================================================
// Kernel 3: fused convert+projection via mma.sync
//   yT[ab][d][n] = bf16( rinv[n] * sum_k WT[d][k] * bf16(x[ab][n][k]) )
// CTA: 128d x 128n, 512 threads, 16 warps (4d x 4n), warp tile 32x32.
// grid (16 n-tiles, 16 ab).
// ============================================================
#define PTILE_B (128 * 128)   // one 64-k chunk tile: 128 rows x 128B = 16 KB

__global__ void __launch_bounds__(512, 1)
project_mma(const float* __restrict__ x) {
    extern __shared__ char smem_raw[];
    const uint32_t sbase = (smem_u32(smem_raw) + 127) & ~127u;
    const uint32_t Ao0 = sbase;                  // WT chunks: 2 x 16KB
    const uint32_t Bo0 = sbase + 2 * PTILE_B;    // x-bf16 chunks: 2 x 16KB

    const int tid  = threadIdx.x;
    const int wid  = tid >> 5;
    const int lane = tid & 31;
    const int warp_m = (wid & 3) * 32;     // d
    const int warp_d = (wid >> 2) * 32;    // n (local)
    const int n0 = blockIdx.x * 128;
    const int ab = blockIdx.y;

    // WT via cp.async into swizzled A tiles
    {
        const char* Ag = (const char*)g_wt;
        const int lrow = tid >> 2;
        const int lc0  = (tid & 3) * 2;
#pragma unroll
        for (int c = 0; c < 2; ++c)
#pragma unroll
            for (int i = 0; i < 2; ++i) {
                int ch = lc0 + i;
                uint32_t sw = (uint32_t)(ch ^ (lrow & 7)) * 16 + (uint32_t)lrow * 128;
                size_t goff = ((size_t)lrow * DIN + c * 64 + ch * 8) * 2;
                cp_async16(Ao0 + c * PTILE_B + sw, Ag + goff);
            }
        cp_commit();
    }

    // x fp32 -> bf16 swizzled B tiles, in registers
    {
        const float* xab = x + ((size_t)ab * NN + n0) * DIN;
        const int f4c = tid & 31;
        const int chunk = f4c >> 4;
        const int ku    = (f4c & 15) >> 1;
        const int half  = f4c & 1;
#pragma unroll
        for (int i = 0; i < 8; ++i) {
            const int row = (tid >> 5) + i * 16;
            float4 v = *(const float4*)&xab[(size_t)row * DIN + f4c * 4];
            uint32_t lo = pack_bf2(v.x, v.y);
            uint32_t hi = pack_bf2(v.z, v.w);
            uint32_t addr = Bo0 + chunk * PTILE_B + (uint32_t)row * 128
                          + (uint32_t)(ku ^ (row & 7)) * 16 + half * 8;
            asm volatile("st.shared.v2.b32 [%0], {%1, %2};" :: "r"(addr), "r"(lo), "r"(hi));
        }
    }
    cp_wait<0>();
    __syncthreads();

    float acc[2][4][4];
#pragma unroll
    for (int mf = 0; mf < 2; ++mf)
#pragma unroll
        for (int nf = 0; nf < 4; ++nf)
#pragma unroll
            for (int e = 0; e < 4; ++e) acc[mf][nf][e] = 0.f;

    const int portion = lane >> 3;
    const int w8 = lane & 7;

#pragma unroll
    for (int c = 0; c < 2; ++c) {
        const uint32_t Ao = Ao0 + c * PTILE_B;
        const uint32_t Bo = Bo0 + c * PTILE_B;
#pragma unroll
        for (int ks = 0; ks < 4; ++ks) {
            const int kb8 = ks * 2;
            uint32_t a[2][4], b[4][2];
#pragma unroll
            for (int mf = 0; mf < 2; ++mf) {
                int row = warp_m + mf * 16 + (portion & 1) * 8 + w8;
                int ch  = kb8 + (portion >> 1);
                ldsm_x4(a[mf], Ao + (uint32_t)row * 128 + (uint32_t)(ch ^ (row & 7)) * 16);
            }
#pragma unroll
            for (int nfp = 0; nfp < 2; ++nfp) {
                int row = warp_d + nfp * 16 + (portion >> 1) * 8 + w8;
                int ch  = kb8 + (portion & 1);
                uint32_t r[4];
                ldsm_x4(r, Bo + (uint32_t)row * 128 + (uint32_t)(ch ^ (row & 7)) * 16);
                b[2 * nfp][0]     = r[0];
                b[2 * nfp][1]     = r[1];
                b[2 * nfp + 1][0] = r[2];
                b[2 * nfp + 1][1] = r[3];
            }
#pragma unroll
            for (int mf = 0; mf < 2; ++mf)
#pragma unroll
                for (int nf = 0; nf < 4; ++nf)
                    mma16816(acc[mf][nf], a[mf], b[nf]);
        }
    }

    const int g  = lane >> 2;
    const int tc = lane & 3;
    char* yT = (char*)(g_yT + (size_t)ab * DOUT * NN);
#pragma unroll
    for (int mf = 0; mf < 2; ++mf) {
        const int d0g = warp_m + mf * 16 + g;
#pragma unroll
        for (int nf = 0; nf < 4; ++nf) {
            const int ng = n0 + warp_d + nf * 8 + tc * 2;
            const float rv0 = g_rinv[ng];
            const float rv1 = g_rinv[ng + 1];
            *(uint32_t*)(yT + ((size_t)d0g * NN + ng) * 2) =
                pack_bf2(acc[mf][nf][0] * rv0, acc[mf][nf][1] * rv1);
            *(uint32_t*)(yT + ((size_t)(d0g + 8) * NN + ng) * 2) =
                pack_bf2(acc[mf][nf][2] * rv0, acc[mf][nf][3] * rv1);
        }
    }
}

// ============================================================
// Kernel 4: mma.sync bf16 aggregate (v7: 256m x 128d, 4-stage, 1 barrier/chunk)
//   out[ab][m][d] = relu( rinv[m] * sum_n adjT[m][n]*yT[ab][d][n] + bias[d] )
// 512 threads, 16 warps (4m x 4d), warp tile 64m x 32d. BK=64.
// A tile 256x64 (32KB), B tile 128x64 (16KB), 4 stages (192KB), prefetch 3.
// grid (8 m-tiles, 16 ab) = 128 CTAs = one wave.
// ============================================================
#define A_TILE_B  (256 * 128)          // 32 KB
#define B_TILE_B  (128 * 128)          // 16 KB
#define STAGE_B   (A_TILE_B + B_TILE_B) // 48 KB
#define NSTAGES   4
#define NCHUNKS   32                   // 2048 / 64

__global__ void __launch_bounds__(512, 1)
aggregate_mma(const float* __restrict__ bias, float* __restrict__ out) {
    extern __shared__ char smem_raw[];
    const uint32_t sbase = (smem_u32(smem_raw) + 127) & ~127u;

    const int tid  = threadIdx.x;
    const int wid  = tid >> 5;
    const int lane = tid & 31;
    const int warp_m = (wid & 3) * 64;     // 0,64,128,192
    const int warp_d = (wid >> 2) * 32;    // 0,32,64,96
    const int m0   = blockIdx.x * 256;
    const int ab   = blockIdx.y;

    const char* Ag = (const char*)(g_adjT + (size_t)m0 * NN);
    const char* Bg = (const char*)(g_yT + (size_t)ab * DOUT * NN);

    const int arow = tid >> 1;            // 0..255
    const int aq   = (tid & 1) * 4;       // 0 or 4
    const int brow = tid >> 2;            // 0..127
    const int bq   = (tid & 3) * 2;       // 0,2,4,6

    auto load_buf = [&](int buf, int c) {
        const uint32_t Ao = sbase + buf * STAGE_B;
        const uint32_t Bo = Ao + A_TILE_B;
        const size_t An = (size_t)arow * NN + (size_t)c * 64;
        const size_t Bn = (size_t)brow * NN + (size_t)c * 64;
#pragma unroll
        for (int i = 0; i < 4; ++i) {
            int ch = aq + i;
            uint32_t sw = (uint32_t)(ch ^ (arow & 7)) * 16 + (uint32_t)arow * 128;
            cp_async16(Ao + sw, Ag + (An + ch * 8) * 2);
        }
#pragma unroll
        for (int i = 0; i < 2; ++i) {
            int ch = bq + i;
            uint32_t sw = (uint32_t)(ch ^ (brow & 7)) * 16 + (uint32_t)brow * 128;
            cp_async16(Bo + sw, Bg + (Bn + ch * 8) * 2);
        }
        cp_commit();
    };

    float acc[4][4][4];
#pragma unroll
    for (int mf = 0; mf < 4; ++mf)
#pragma unroll
        for (int nf = 0; nf < 4; ++nf)
#pragma unroll
            for (int e = 0; e < 4; ++e) acc[mf][nf][e] = 0.f;

    load_buf(0, 0);
    load_buf(1, 1);
    load_buf(2, 2);

    const int portion = lane >> 3;
    const int w8 = lane & 7;

    for (int c = 0; c < NCHUNKS; ++c) {
        if (c + 2 < NCHUNKS)      cp_wait<2>();
        else if (c + 1 < NCHUNKS) cp_wait<1>();
        else                      cp_wait<0>();
        __syncthreads();
        if (c + 3 < NCHUNKS) load_buf((c + 3) & 3, c + 3);

        const uint32_t Ao = sbase + (c & 3) * STAGE_B;
        const uint32_t Bo = Ao + A_TILE_B;

#pragma unroll
        for (int ks = 0; ks < 4; ++ks) {
            const int kb8 = ks * 2;
            uint32_t a[4][4], b[4][2];
#pragma unroll
            for (int mf = 0; mf < 4; ++mf) {
                int row = warp_m + mf * 16 + (portion & 1) * 8 + w8;
                int ch  = kb8 + (portion >> 1);
                ldsm_x4(a[mf], Ao + (uint32_t)row * 128 + (uint32_t)(ch ^ (row & 7)) * 16);
            }
#pragma unroll
            for (int nfp = 0; nfp < 2; ++nfp) {
                int row = warp_d + nfp * 16 + (portion >> 1) * 8 + w8;
                int ch  = kb8 + (portion & 1);
                uint32_t r[4];
                ldsm_x4(r, Bo + (uint32_t)row * 128 + (uint32_t)(ch ^ (row & 7)) * 16);
                b[2 * nfp][0]     = r[0];
                b[2 * nfp][1]     = r[1];
                b[2 * nfp + 1][0] = r[2];
                b[2 * nfp + 1][1] = r[3];
            }
#pragma unroll
            for (int mf = 0; mf < 4; ++mf)
#pragma unroll
                for (int nf = 0; nf < 4; ++nf)
                    mma16816(acc[mf][nf], a[mf], b[nf]);
        }
        // no trailing barrier: with 4 stages, the stage written at top of
        // chunk c+1 ((c+4)&3 = c&3... written AFTER the top barrier of c+1,
        // which all warps reach only after finishing chunk c's MMAs.
    }

    const int g  = lane >> 2;
    const int tc = lane & 3;
    float* outab = out + (size_t)ab * NN * DOUT;
#pragma unroll
    for (int mf = 0; mf < 4; ++mf) {
        const int mrow0 = m0 + warp_m + mf * 16 + g;
        const float rv0 = g_rinv[mrow0];
        const float rv1 = g_rinv[mrow0 + 8];
#pragma unroll
        for (int nf = 0; nf < 4; ++nf) {
            const int d0 = warp_d + nf * 8 + tc * 2;
            const float b0 = __ldg(&bias[d0]);
            const float b1 = __ldg(&bias[d0 + 1]);
            float2 v0, v1;
            v0.x = fmaxf(fmaf(acc[mf][nf][0], rv0, b0), 0.f);
            v0.y = fmaxf(fmaf(acc[mf][nf][1], rv0, b1), 0.f);
            v1.x = fmaxf(fmaf(acc[mf][nf][2], rv1, b0), 0.f);
            v1.y = fmaxf(fmaf(acc[mf][nf][3], rv1, b1), 0.f);
            *(float2*)&outab[(size_t)mrow0 * DOUT + d0]       = v0;
            *(float2*)&outab[(size_t)(mrow0 + 8) * DOUT + d0] = v1;
        }
    }
}

// ============================================================
extern "C" void kernel_launch(void* const* d_in, const int* in_sizes, int n_in,
                              void* d_out, int out_size) {
    const float* adj  = (const float*)d_in[0];
    const float* x    = (const float*)d_in[1];
    const float* w    = (const float*)d_in[2];
    const float* bias = (const float*)d_in[3];
    float* out        = (float*)d_out;

    const int agg_smem  = NSTAGES * STAGE_B + 256;   // 192 KB + slack
    const int proj_smem = 4 * PTILE_B + 256;         // 64 KB + slack
    cudaFuncSetAttribute(aggregate_mma, cudaFuncAttributeMaxDynamicSharedMemorySize, agg_smem);
    cudaFuncSetAttribute(project_mma, cudaFuncAttributeMaxDynamicSharedMemorySize, proj_smem);

    transpose_colsum_kernel<<<dim3(32, 32), 256>>>(adj);
    rinv_wt_kernel<<<16, 256>>>(w);
    project_mma<<<dim3(16, 16), 512, proj_smem>>>(x);
    aggregate_mma<<<dim3(8, 16), 512, agg_smem>>>(bias, out);
}

// round 14
// speedup vs baseline: 1.1891x; 1.0037x over previous
#include <cuda_runtime.h>
#include <cuda_bf16.h>
#include <cstdint>

// dims fixed by setup_inputs
#define NN     2048
#define ABATCH 16
#define DIN    128
#define DOUT   128
#define TCHUNKS 32

// ---------------- device scratch (no allocs allowed) ----------------
__device__ float g_part[TCHUNKS * NN];
__device__ __nv_bfloat16 g_adjT[(size_t)NN * NN];           // adjT[m][n], 8 MB
__device__ __nv_bfloat16 g_yT[(size_t)ABATCH * DOUT * NN];  // yT[ab][d][n], 8 MB
__device__ __nv_bfloat16 g_wt[DOUT * DIN];                  // WT[d][k] bf16

__device__ __forceinline__ uint32_t smem_u32(const void* p) {
    return (uint32_t)__cvta_generic_to_shared(p);
}
__device__ __forceinline__ void cp_async16(uint32_t dst, const void* src) {
    asm volatile("cp.async.cg.shared.global [%0], [%1], 16;" :: "r"(dst), "l"(src));
}
__device__ __forceinline__ void cp_commit() {
    asm volatile("cp.async.commit_group;" ::: "memory");
}
template <int N>
__device__ __forceinline__ void cp_wait() {
    asm volatile("cp.async.wait_group %0;" :: "n"(N) : "memory");
}
__device__ __forceinline__ void ldsm_x4(uint32_t* r, uint32_t addr) {
    asm volatile("ldmatrix.sync.aligned.m8n8.x4.shared.b16 {%0,%1,%2,%3}, [%4];"
                 : "=r"(r[0]), "=r"(r[1]), "=r"(r[2]), "=r"(r[3]) : "r"(addr));
}
__device__ __forceinline__ void mma16816(float* d, const uint32_t* a, const uint32_t* b) {
    asm volatile(
        "mma.sync.aligned.m16n8k16.row.col.f32.bf16.bf16.f32 "
        "{%0,%1,%2,%3}, {%4,%5,%6,%7}, {%8,%9}, {%0,%1,%2,%3};"
        : "+f"(d[0]), "+f"(d[1]), "+f"(d[2]), "+f"(d[3])
        : "r"(a[0]), "r"(a[1]), "r"(a[2]), "r"(a[3]), "r"(b[0]), "r"(b[1]));
}
__device__ __forceinline__ uint32_t pack_bf2(float a, float b) {
    __nv_bfloat162 t = __floats2bfloat162_rn(a, b);
    return *(uint32_t*)&t;
}

// ============================================================
// Kernel 1: fused transpose + partial column sums (64x64 tiles)
//           + WT build (grid row y=32, blocks x<8)
// grid (32, 33), 256 threads
// ============================================================
__global__ void __launch_bounds__(256) transpose_colsum_kernel(const float* __restrict__ adj,
                                                               const float* __restrict__ w) {
    if (blockIdx.y == 32) {
        // WT[d][k] = bf16(W[k][d]) : 8 blocks x 256 threads x 8 elems = 16384
        if (blockIdx.x >= 8) return;
        int idx = (blockIdx.x * 256 + threadIdx.x) * 8;
        int d  = idx >> 7;
        int k0 = idx & 127;
        uint4 pk;
        float a0 = w[(size_t)(k0 + 0) * DOUT + d], a1 = w[(size_t)(k0 + 1) * DOUT + d];
        float a2 = w[(size_t)(k0 + 2) * DOUT + d], a3 = w[(size_t)(k0 + 3) * DOUT + d];
        float a4 = w[(size_t)(k0 + 4) * DOUT + d], a5 = w[(size_t)(k0 + 5) * DOUT + d];
        float a6 = w[(size_t)(k0 + 6) * DOUT + d], a7 = w[(size_t)(k0 + 7) * DOUT + d];
        pk.x = pack_bf2(a0, a1);
        pk.y = pack_bf2(a2, a3);
        pk.z = pack_bf2(a4, a5);
        pk.w = pack_bf2(a6, a7);
        *(uint4*)((char*)g_wt + (size_t)idx * 2) = pk;
        return;
    }

    __shared__ float t[64][65];
    const int mx = blockIdx.x * 64, ny = blockIdx.y * 64;
    const int tid = threadIdx.x;
    const int row = tid >> 2;
    const int q   = tid & 3;

#pragma unroll
    for (int i = 0; i < 4; ++i) {
        const int f4 = q + 4 * i;
        float4 v = *(const float4*)&adj[(size_t)(ny + row) * NN + mx + f4 * 4];
        t[row][f4 * 4 + 0] = v.x;
        t[row][f4 * 4 + 1] = v.y;
        t[row][f4 * 4 + 2] = v.z;
        t[row][f4 * 4 + 3] = v.w;
    }
    __syncthreads();

    const int m  = row;
    const int nq = q * 16;
    float vv[16];
    float s = 0.f;
#pragma unroll
    for (int j = 0; j < 16; ++j) {
        vv[j] = t[nq + j][m];
        s += vv[j];
    }
    uint4 p0, p1;
    p0.x = pack_bf2(vv[0],  vv[1]);  p0.y = pack_bf2(vv[2],  vv[3]);
    p0.z = pack_bf2(vv[4],  vv[5]);  p0.w = pack_bf2(vv[6],  vv[7]);
    p1.x = pack_bf2(vv[8],  vv[9]);  p1.y = pack_bf2(vv[10], vv[11]);
    p1.z = pack_bf2(vv[12], vv[13]); p1.w = pack_bf2(vv[14], vv[15]);
    char* dst = (char*)g_adjT + ((size_t)(mx + m) * NN + ny + nq) * 2;
    *(uint4*)dst        = p0;
    *(uint4*)(dst + 16) = p1;

    s += __shfl_xor_sync(0xFFFFFFFF, s, 1);
    s += __shfl_xor_sync(0xFFFFFFFF, s, 2);
    if (q == 0) g_part[blockIdx.y * NN + mx + m] = s;
}

// ============================================================
// Kernel 2: fused convert+projection via mma.sync; rinv computed in-kernel
//   yT[ab][d][n] = bf16( rinv[n] * sum_k WT[d][k] * bf16(x[ab][n][k]) )
// CTA: 128d x 128n, 512 threads, 16 warps (4d x 4n), warp tile 32x32.
// grid (16 n-tiles, 16 ab).
// ============================================================
#define PTILE_B (128 * 128)   // one 64-k chunk tile: 128 rows x 128B = 16 KB

__global__ void __launch_bounds__(512, 1)
project_mma(const float* __restrict__ x) {
    extern __shared__ char smem_raw[];
    __shared__ float rinv_s[128];
    const uint32_t sbase = (smem_u32(smem_raw) + 127) & ~127u;
    const uint32_t Ao0 = sbase;                  // WT chunks: 2 x 16KB
    const uint32_t Bo0 = sbase + 2 * PTILE_B;    // x-bf16 chunks: 2 x 16KB

    const int tid  = threadIdx.x;
    const int wid  = tid >> 5;
    const int lane = tid & 31;
    const int warp_m = (wid & 3) * 32;     // d
    const int warp_d = (wid >> 2) * 32;    // n (local)
    const int n0 = blockIdx.x * 128;
    const int ab = blockIdx.y;

    // WT via cp.async into swizzled A tiles
    {
        const char* Ag = (const char*)g_wt;
        const int lrow = tid >> 2;
        const int lc0  = (tid & 3) * 2;
#pragma unroll
        for (int c = 0; c < 2; ++c)
#pragma unroll
            for (int i = 0; i < 2; ++i) {
                int ch = lc0 + i;
                uint32_t sw = (uint32_t)(ch ^ (lrow & 7)) * 16 + (uint32_t)lrow * 128;
                size_t goff = ((size_t)lrow * DIN + c * 64 + ch * 8) * 2;
                cp_async16(Ao0 + c * PTILE_B + sw, Ag + goff);
            }
        cp_commit();
    }

    // x fp32 -> bf16 swizzled B tiles, in registers
    {
        const float* xab = x + ((size_t)ab * NN + n0) * DIN;
        const int f4c = tid & 31;
        const int chunk = f4c >> 4;
        const int ku    = (f4c & 15) >> 1;
        const int half  = f4c & 1;
#pragma unroll
        for (int i = 0; i < 8; ++i) {
            const int row = (tid >> 5) + i * 16;
            float4 v = *(const float4*)&xab[(size_t)row * DIN + f4c * 4];
            uint32_t lo = pack_bf2(v.x, v.y);
            uint32_t hi = pack_bf2(v.z, v.w);
            uint32_t addr = Bo0 + chunk * PTILE_B + (uint32_t)row * 128
                          + (uint32_t)(ku ^ (row & 7)) * 16 + half * 8;
            asm volatile("st.shared.v2.b32 [%0], {%1, %2};" :: "r"(addr), "r"(lo), "r"(hi));
        }
    }

    // rinv for this CTA's 128 n-columns (same summation order as before)
    if (tid < 128) {
        float s = 0.f;
#pragma unroll
        for (int c = 0; c < TCHUNKS; ++c)
            s += g_part[c * NN + n0 + tid];
        rinv_s[tid] = rsqrtf(s);
    }

    cp_wait<0>();
    __syncthreads();

    float acc[2][4][4];
#pragma unroll
    for (int mf = 0; mf < 2; ++mf)
#pragma unroll
        for (int nf = 0; nf < 4; ++nf)
#pragma unroll
            for (int e = 0; e < 4; ++e) acc[mf][nf][e] = 0.f;

    const int portion = lane >> 3;
    const int w8 = lane & 7;

#pragma unroll
    for (int c = 0; c < 2; ++c) {
        const uint32_t Ao = Ao0 + c * PTILE_B;
        const uint32_t Bo = Bo0 + c * PTILE_B;
#pragma unroll
        for (int ks = 0; ks < 4; ++ks) {
            const int kb8 = ks * 2;
            uint32_t a[2][4], b[4][2];
#pragma unroll
            for (int mf = 0; mf < 2; ++mf) {
                int row = warp_m + mf * 16 + (portion & 1) * 8 + w8;
                int ch  = kb8 + (portion >> 1);
                ldsm_x4(a[mf], Ao + (uint32_t)row * 128 + (uint32_t)(ch ^ (row & 7)) * 16);
            }
#pragma unroll
            for (int nfp = 0; nfp < 2; ++nfp) {
                int row = warp_d + nfp * 16 + (portion >> 1) * 8 + w8;
                int ch  = kb8 + (portion & 1);
                uint32_t r[4];
                ldsm_x4(r, Bo + (uint32_t)row * 128 + (uint32_t)(ch ^ (row & 7)) * 16);
                b[2 * nfp][0]     = r[0];
                b[2 * nfp][1]     = r[1];
                b[2 * nfp + 1][0] = r[2];
                b[2 * nfp + 1][1] = r[3];
            }
#pragma unroll
            for (int mf = 0; mf < 2; ++mf)
#pragma unroll
                for (int nf = 0; nf < 4; ++nf)
                    mma16816(acc[mf][nf], a[mf], b[nf]);
        }
    }

    const int g  = lane >> 2;
    const int tc = lane & 3;
    char* yT = (char*)(g_yT + (size_t)ab * DOUT * NN);
#pragma unroll
    for (int mf = 0; mf < 2; ++mf) {
        const int d0g = warp_m + mf * 16 + g;
#pragma unroll
        for (int nf = 0; nf < 4; ++nf) {
            const int nl = warp_d + nf * 8 + tc * 2;     // local n
            const int ng = n0 + nl;
            const float rv0 = rinv_s[nl];
            const float rv1 = rinv_s[nl + 1];
            *(uint32_t*)(yT + ((size_t)d0g * NN + ng) * 2) =
                pack_bf2(acc[mf][nf][0] * rv0, acc[mf][nf][1] * rv1);
            *(uint32_t*)(yT + ((size_t)(d0g + 8) * NN + ng) * 2) =
                pack_bf2(acc[mf][nf][2] * rv0, acc[mf][nf][3] * rv1);
        }
    }
}

// ============================================================
// Kernel 3: mma.sync bf16 aggregate (256m x 128d, 4-stage); rinv in-kernel
//   out[ab][m][d] = relu( rinv[m] * sum_n adjT[m][n]*yT[ab][d][n] + bias[d] )
// 512 threads, 16 warps (4m x 4d), warp tile 64m x 32d. BK=64.
// grid (8 m-tiles, 16 ab) = 128 CTAs = one wave.
// ============================================================
#define A_TILE_B  (256 * 128)          // 32 KB
#define B_TILE_B  (128 * 128)          // 16 KB
#define STAGE_B   (A_TILE_B + B_TILE_B) // 48 KB
#define NSTAGES   4
#define NCHUNKS   32                   // 2048 / 64

__global__ void __launch_bounds__(512, 1)
aggregate_mma(const float* __restrict__ bias, float* __restrict__ out) {
    extern __shared__ char smem_raw[];
    __shared__ float rinv_s[256];
    const uint32_t sbase = (smem_u32(smem_raw) + 127) & ~127u;

    const int tid  = threadIdx.x;
    const int wid  = tid >> 5;
    const int lane = tid & 31;
    const int warp_m = (wid & 3) * 64;     // 0,64,128,192
    const int warp_d = (wid >> 2) * 32;    // 0,32,64,96
    const int m0   = blockIdx.x * 256;
    const int ab   = blockIdx.y;

    const char* Ag = (const char*)(g_adjT + (size_t)m0 * NN);
    const char* Bg = (const char*)(g_yT + (size_t)ab * DOUT * NN);

    const int arow = tid >> 1;            // 0..255
    const int aq   = (tid & 1) * 4;       // 0 or 4
    const int brow = tid >> 2;            // 0..127
    const int bq   = (tid & 3) * 2;       // 0,2,4,6

    auto load_buf = [&](int buf, int c) {
        const uint32_t Ao = sbase + buf * STAGE_B;
        const uint32_t Bo = Ao + A_TILE_B;
        const size_t An = (size_t)arow * NN + (size_t)c * 64;
        const size_t Bn = (size_t)brow * NN + (size_t)c * 64;
#pragma unroll
        for (int i = 0; i < 4; ++i) {
            int ch = aq + i;
            uint32_t sw = (uint32_t)(ch ^ (arow & 7)) * 16 + (uint32_t)arow * 128;
            cp_async16(Ao + sw, Ag + (An + ch * 8) * 2);
        }
#pragma unroll
        for (int i = 0; i < 2; ++i) {
            int ch = bq + i;
            uint32_t sw = (uint32_t)(ch ^ (brow & 7)) * 16 + (uint32_t)brow * 128;
            cp_async16(Bo + sw, Bg + (Bn + ch * 8) * 2);
        }
        cp_commit();
    };

    float acc[4][4][4];
#pragma unroll
    for (int mf = 0; mf < 4; ++mf)
#pragma unroll
        for (int nf = 0; nf < 4; ++nf)
#pragma unroll
            for (int e = 0; e < 4; ++e) acc[mf][nf][e] = 0.f;

    load_buf(0, 0);
    load_buf(1, 1);
    load_buf(2, 2);

    // rinv for this CTA's 256 m-rows (same summation order as before)
    if (tid < 256) {
        float s = 0.f;
#pragma unroll
        for (int c = 0; c < TCHUNKS; ++c)
            s += g_part[c * NN + m0 + tid];
        rinv_s[tid] = rsqrtf(s);
    }

    const int portion = lane >> 3;
    const int w8 = lane & 7;

    for (int c = 0; c < NCHUNKS; ++c) {
        if (c + 2 < NCHUNKS)      cp_wait<2>();
        else if (c + 1 < NCHUNKS) cp_wait<1>();
        else                      cp_wait<0>();
        __syncthreads();
        if (c + 3 < NCHUNKS) load_buf((c + 3) & 3, c + 3);

        const uint32_t Ao = sbase + (c & 3) * STAGE_B;
        const uint32_t Bo = Ao + A_TILE_B;

#pragma unroll
        for (int ks = 0; ks < 4; ++ks) {
            const int kb8 = ks * 2;
            uint32_t a[4][4], b[4][2];
#pragma unroll
            for (int mf = 0; mf < 4; ++mf) {
                int row = warp_m + mf * 16 + (portion & 1) * 8 + w8;
                int ch  = kb8 + (portion >> 1);
                ldsm_x4(a[mf], Ao + (uint32_t)row * 128 + (uint32_t)(ch ^ (row & 7)) * 16);
            }
#pragma unroll
            for (int nfp = 0; nfp < 2; ++nfp) {
                int row = warp_d + nfp * 16 + (portion >> 1) * 8 + w8;
                int ch  = kb8 + (portion & 1);
                uint32_t r[4];
                ldsm_x4(r, Bo + (uint32_t)row * 128 + (uint32_t)(ch ^ (row & 7)) * 16);
                b[2 * nfp][0]     = r[0];
                b[2 * nfp][1]     = r[1];
                b[2 * nfp + 1][0] = r[2];
                b[2 * nfp + 1][1] = r[3];
            }
#pragma unroll
            for (int mf = 0; mf < 4; ++mf)
#pragma unroll
                for (int nf = 0; nf < 4; ++nf)
                    mma16816(acc[mf][nf], a[mf], b[nf]);
        }
    }

    const int g  = lane >> 2;
    const int tc = lane & 3;
    float* outab = out + (size_t)ab * NN * DOUT;
#pragma unroll
    for (int mf = 0; mf < 4; ++mf) {
        const int ml = warp_m + mf * 16 + g;        // local m
        const int mrow0 = m0 + ml;
        const float rv0 = rinv_s[ml];
        const float rv1 = rinv_s[ml + 8];
#pragma unroll
        for (int nf = 0; nf < 4; ++nf) {
            const int d0 = warp_d + nf * 8 + tc * 2;
            const float b0 = __ldg(&bias[d0]);
            const float b1 = __ldg(&bias[d0 + 1]);
            float2 v0, v1;
            v0.x = fmaxf(fmaf(acc[mf][nf][0], rv0, b0), 0.f);
            v0.y = fmaxf(fmaf(acc[mf][nf][1], rv0, b1), 0.f);
            v1.x = fmaxf(fmaf(acc[mf][nf][2], rv1, b0), 0.f);
            v1.y = fmaxf(fmaf(acc[mf][nf][3], rv1, b1), 0.f);
            *(float2*)&outab[(size_t)mrow0 * DOUT + d0]       = v0;
            *(float2*)&outab[(size_t)(mrow0 + 8) * DOUT + d0] = v1;
        }
    }
}

// ============================================================
extern "C" void kernel_launch(void* const* d_in, const int* in_sizes, int n_in,
                              void* d_out, int out_size) {
    const float* adj  = (const float*)d_in[0];
    const float* x    = (const float*)d_in[1];
    const float* w    = (const float*)d_in[2];
    const float* bias = (const float*)d_in[3];
    float* out        = (float*)d_out;

    const int agg_smem  = NSTAGES * STAGE_B + 256;   // 192 KB + slack
    const int proj_smem = 4 * PTILE_B + 256;         // 64 KB + slack
    cudaFuncSetAttribute(aggregate_mma, cudaFuncAttributeMaxDynamicSharedMemorySize, agg_smem);
    cudaFuncSetAttribute(project_mma, cudaFuncAttributeMaxDynamicSharedMemorySize, proj_smem);

    transpose_colsum_kernel<<<dim3(32, 33), 256>>>(adj, w);
    project_mma<<<dim3(16, 16), 512, proj_smem>>>(x);
    aggregate_mma<<<dim3(8, 16), 512, agg_smem>>>(bias, out);
}

// round 15
// speedup vs baseline: 1.1904x; 1.0011x over previous
#include <cuda_runtime.h>
#include <cuda_bf16.h>
#include <cstdint>

// dims fixed by setup_inputs
#define NN     2048
#define ABATCH 16
#define DIN    128
#define DOUT   128
#define TCHUNKS 32

// ---------------- device scratch (no allocs allowed) ----------------
__device__ float g_part[TCHUNKS * NN];
__device__ __nv_bfloat16 g_adjT[(size_t)NN * NN];           // adjT[m][n], 8 MB
__device__ __nv_bfloat16 g_yT[(size_t)ABATCH * DOUT * NN];  // yT[ab][d][n], 8 MB
__device__ __nv_bfloat16 g_wt[DOUT * DIN];                  // WT[d][k] bf16

__device__ __forceinline__ uint32_t smem_u32(const void* p) {
    return (uint32_t)__cvta_generic_to_shared(p);
}
__device__ __forceinline__ void cp_async16(uint32_t dst, const void* src) {
    asm volatile("cp.async.cg.shared.global [%0], [%1], 16;" :: "r"(dst), "l"(src));
}
__device__ __forceinline__ void cp_commit() {
    asm volatile("cp.async.commit_group;" ::: "memory");
}
template <int N>
__device__ __forceinline__ void cp_wait() {
    asm volatile("cp.async.wait_group %0;" :: "n"(N) : "memory");
}
__device__ __forceinline__ void ldsm_x4(uint32_t* r, uint32_t addr) {
    asm volatile("ldmatrix.sync.aligned.m8n8.x4.shared.b16 {%0,%1,%2,%3}, [%4];"
                 : "=r"(r[0]), "=r"(r[1]), "=r"(r[2]), "=r"(r[3]) : "r"(addr));
}
__device__ __forceinline__ void mma16816(float* d, const uint32_t* a, const uint32_t* b) {
    asm volatile(
        "mma.sync.aligned.m16n8k16.row.col.f32.bf16.bf16.f32 "
        "{%0,%1,%2,%3}, {%4,%5,%6,%7}, {%8,%9}, {%0,%1,%2,%3};"
        : "+f"(d[0]), "+f"(d[1]), "+f"(d[2]), "+f"(d[3])
        : "r"(a[0]), "r"(a[1]), "r"(a[2]), "r"(a[3]), "r"(b[0]), "r"(b[1]));
}
__device__ __forceinline__ uint32_t pack_bf2(float a, float b) {
    __nv_bfloat162 t = __floats2bfloat162_rn(a, b);
    return *(uint32_t*)&t;
}

// ============================================================
// Kernel 1 (v3): fused transpose + partial column sums, 2 tiles/block
//   Each block: 128 m x 64 n (two 64x64 tiles), cp.async loads (MLP 8).
//   + WT build (grid row y=32, blocks x<8).
// grid (16, 33), 256 threads
// ============================================================
#define TP_PITCH 68   // floats per smem row (16B-aligned, 2-way bank conflict max)

__global__ void __launch_bounds__(256) transpose_colsum_kernel(const float* __restrict__ adj,
                                                               const float* __restrict__ w) {
    if (blockIdx.y == 32) {
        // WT[d][k] = bf16(W[k][d]) : 8 blocks x 256 threads x 8 elems = 16384
        if (blockIdx.x >= 8) return;
        int idx = (blockIdx.x * 256 + threadIdx.x) * 8;
        int d  = idx >> 7;
        int k0 = idx & 127;
        uint4 pk;
        float a0 = w[(size_t)(k0 + 0) * DOUT + d], a1 = w[(size_t)(k0 + 1) * DOUT + d];
        float a2 = w[(size_t)(k0 + 2) * DOUT + d], a3 = w[(size_t)(k0 + 3) * DOUT + d];
        float a4 = w[(size_t)(k0 + 4) * DOUT + d], a5 = w[(size_t)(k0 + 5) * DOUT + d];
        float a6 = w[(size_t)(k0 + 6) * DOUT + d], a7 = w[(size_t)(k0 + 7) * DOUT + d];
        pk.x = pack_bf2(a0, a1);
        pk.y = pack_bf2(a2, a3);
        pk.z = pack_bf2(a4, a5);
        pk.w = pack_bf2(a6, a7);
        *(uint4*)((char*)g_wt + (size_t)idx * 2) = pk;
        return;
    }

    __shared__ float t[2][64][TP_PITCH];
    const int mx0 = blockIdx.x * 128, ny = blockIdx.y * 64;
    const int tid = threadIdx.x;
    const int row = tid >> 2;          // 0..63 (n within tile)
    const int q   = tid & 3;
    const uint32_t tbase = smem_u32(&t[0][0][0]);

    // front-batched loads: 8 cp.async per thread (2 tiles x 4 f4)
#pragma unroll
    for (int ti = 0; ti < 2; ++ti) {
#pragma unroll
        for (int i = 0; i < 4; ++i) {
            const int f4 = q + 4 * i;      // 0..15
            uint32_t dst = tbase + (uint32_t)((ti * 64 + row) * TP_PITCH + f4 * 4) * 4;
            cp_async16(dst, &adj[(size_t)(ny + row) * NN + mx0 + ti * 64 + f4 * 4]);
        }
    }
    cp_commit();
    cp_wait<0>();
    __syncthreads();

    const int m  = row;                // m within tile
    const int nq = q * 16;
#pragma unroll
    for (int ti = 0; ti < 2; ++ti) {
        float vv[16];
        float s = 0.f;
#pragma unroll
        for (int j = 0; j < 16; ++j) {
            vv[j] = t[ti][nq + j][m];
            s += vv[j];
        }
        uint4 p0, p1;
        p0.x = pack_bf2(vv[0],  vv[1]);  p0.y = pack_bf2(vv[2],  vv[3]);
        p0.z = pack_bf2(vv[4],  vv[5]);  p0.w = pack_bf2(vv[6],  vv[7]);
        p1.x = pack_bf2(vv[8],  vv[9]);  p1.y = pack_bf2(vv[10], vv[11]);
        p1.z = pack_bf2(vv[12], vv[13]); p1.w = pack_bf2(vv[14], vv[15]);
        char* dst = (char*)g_adjT + ((size_t)(mx0 + ti * 64 + m) * NN + ny + nq) * 2;
        *(uint4*)dst        = p0;
        *(uint4*)(dst + 16) = p1;

        // reduce partials across the 4 q-lanes (same tree as before: (q0+q1)+(q2+q3))
        s += __shfl_xor_sync(0xFFFFFFFF, s, 1);
        s += __shfl_xor_sync(0xFFFFFFFF, s, 2);
        if (q == 0) g_part[blockIdx.y * NN + mx0 + ti * 64 + m] = s;
    }
}

// ============================================================
// Kernel 2: fused convert+projection via mma.sync; rinv computed in-kernel
//   yT[ab][d][n] = bf16( rinv[n] * sum_k WT[d][k] * bf16(x[ab][n][k]) )
// CTA: 128d x 128n, 512 threads, 16 warps (4d x 4n), warp tile 32x32.
// grid (16 n-tiles, 16 ab).
// ============================================================
#define PTILE_B (128 * 128)   // one 64-k chunk tile: 128 rows x 128B = 16 KB

__global__ void __launch_bounds__(512, 1)
project_mma(const float* __restrict__ x) {
    extern __shared__ char smem_raw[];
    __shared__ float rinv_s[128];
    const uint32_t sbase = (smem_u32(smem_raw) + 127) & ~127u;
    const uint32_t Ao0 = sbase;                  // WT chunks: 2 x 16KB
    const uint32_t Bo0 = sbase + 2 * PTILE_B;    // x-bf16 chunks: 2 x 16KB

    const int tid  = threadIdx.x;
    const int wid  = tid >> 5;
    const int lane = tid & 31;
    const int warp_m = (wid & 3) * 32;     // d
    const int warp_d = (wid >> 2) * 32;    // n (local)
    const int n0 = blockIdx.x * 128;
    const int ab = blockIdx.y;

    // WT via cp.async into swizzled A tiles
    {
        const char* Ag = (const char*)g_wt;
        const int lrow = tid >> 2;
        const int lc0  = (tid & 3) * 2;
#pragma unroll
        for (int c = 0; c < 2; ++c)
#pragma unroll
            for (int i = 0; i < 2; ++i) {
                int ch = lc0 + i;
                uint32_t sw = (uint32_t)(ch ^ (lrow & 7)) * 16 + (uint32_t)lrow * 128;
                size_t goff = ((size_t)lrow * DIN + c * 64 + ch * 8) * 2;
                cp_async16(Ao0 + c * PTILE_B + sw, Ag + goff);
            }
        cp_commit();
    }

    // x fp32 -> bf16 swizzled B tiles, in registers
    {
        const float* xab = x + ((size_t)ab * NN + n0) * DIN;
        const int f4c = tid & 31;
        const int chunk = f4c >> 4;
        const int ku    = (f4c & 15) >> 1;
        const int half  = f4c & 1;
#pragma unroll
        for (int i = 0; i < 8; ++i) {
            const int row = (tid >> 5) + i * 16;
            float4 v = *(const float4*)&xab[(size_t)row * DIN + f4c * 4];
            uint32_t lo = pack_bf2(v.x, v.y);
            uint32_t hi = pack_bf2(v.z, v.w);
            uint32_t addr = Bo0 + chunk * PTILE_B + (uint32_t)row * 128
                          + (uint32_t)(ku ^ (row & 7)) * 16 + half * 8;
            asm volatile("st.shared.v2.b32 [%0], {%1, %2};" :: "r"(addr), "r"(lo), "r"(hi));
        }
    }

    // rinv for this CTA's 128 n-columns (same summation order as before)
    if (tid < 128) {
        float s = 0.f;
#pragma unroll
        for (int c = 0; c < TCHUNKS; ++c)
            s += g_part[c * NN + n0 + tid];
        rinv_s[tid] = rsqrtf(s);
    }

    cp_wait<0>();
    __syncthreads();

    float acc[2][4][4];
#pragma unroll
    for (int mf = 0; mf < 2; ++mf)
#pragma unroll
        for (int nf = 0; nf < 4; ++nf)
#pragma unroll
            for (int e = 0; e < 4; ++e) acc[mf][nf][e] = 0.f;

    const int portion = lane >> 3;
    const int w8 = lane & 7;

#pragma unroll
    for (int c = 0; c < 2; ++c) {
        const uint32_t Ao = Ao0 + c * PTILE_B;
        const uint32_t Bo = Bo0 + c * PTILE_B;
#pragma unroll
        for (int ks = 0; ks < 4; ++ks) {
            const int kb8 = ks * 2;
            uint32_t a[2][4], b[4][2];
#pragma unroll
            for (int mf = 0; mf < 2; ++mf) {
                int row = warp_m + mf * 16 + (portion & 1) * 8 + w8;
                int ch  = kb8 + (portion >> 1);
                ldsm_x4(a[mf], Ao + (uint32_t)row * 128 + (uint32_t)(ch ^ (row & 7)) * 16);
            }
#pragma unroll
            for (int nfp = 0; nfp < 2; ++nfp) {
                int row = warp_d + nfp * 16 + (portion >> 1) * 8 + w8;
                int ch  = kb8 + (portion & 1);
                uint32_t r[4];
                ldsm_x4(r, Bo + (uint32_t)row * 128 + (uint32_t)(ch ^ (row & 7)) * 16);
                b[2 * nfp][0]     = r[0];
                b[2 * nfp][1]     = r[1];
                b[2 * nfp + 1][0] = r[2];
                b[2 * nfp + 1][1] = r[3];
            }
#pragma unroll
            for (int mf = 0; mf < 2; ++mf)
#pragma unroll
                for (int nf = 0; nf < 4; ++nf)
                    mma16816(acc[mf][nf], a[mf], b[nf]);
        }
    }

    const int g  = lane >> 2;
    const int tc = lane & 3;
    char* yT = (char*)(g_yT + (size_t)ab * DOUT * NN);
#pragma unroll
    for (int mf = 0; mf < 2; ++mf) {
        const int d0g = warp_m + mf * 16 + g;
#pragma unroll
        for (int nf = 0; nf < 4; ++nf) {
            const int nl = warp_d + nf * 8 + tc * 2;     // local n
            const int ng = n0 + nl;
            const float rv0 = rinv_s[nl];
            const float rv1 = rinv_s[nl + 1];
            *(uint32_t*)(yT + ((size_t)d0g * NN + ng) * 2) =
                pack_bf2(acc[mf][nf][0] * rv0, acc[mf][nf][1] * rv1);
            *(uint32_t*)(yT + ((size_t)(d0g + 8) * NN + ng) * 2) =
                pack_bf2(acc[mf][nf][2] * rv0, acc[mf][nf][3] * rv1);
        }
    }
}

// ============================================================
// Kernel 3: mma.sync bf16 aggregate (256m x 128d, 4-stage); rinv in-kernel
//   out[ab][m][d] = relu( rinv[m] * sum_n adjT[m][n]*yT[ab][d][n] + bias[d] )
// 512 threads, 16 warps (4m x 4d), warp tile 64m x 32d. BK=64.
// grid (8 m-tiles, 16 ab) = 128 CTAs = one wave.
// ============================================================
#define A_TILE_B  (256 * 128)          // 32 KB
#define B_TILE_B  (128 * 128)          // 16 KB
#define STAGE_B   (A_TILE_B + B_TILE_B) // 48 KB
#define NSTAGES   4
#define NCHUNKS   32                   // 2048 / 64

__global__ void __launch_bounds__(512, 1)
aggregate_mma(const float* __restrict__ bias, float* __restrict__ out) {
    extern __shared__ char smem_raw[];
    __shared__ float rinv_s[256];
    const uint32_t sbase = (smem_u32(smem_raw) + 127) & ~127u;

    const int tid  = threadIdx.x;
    const int wid  = tid >> 5;
    const int lane = tid & 31;
    const int warp_m = (wid & 3) * 64;     // 0,64,128,192
    const int warp_d = (wid >> 2) * 32;    // 0,32,64,96
    const int m0   = blockIdx.x * 256;
    const int ab   = blockIdx.y;

    const char* Ag = (const char*)(g_adjT + (size_t)m0 * NN);
    const char* Bg = (const char*)(g_yT + (size_t)ab * DOUT * NN);

    const int arow = tid >> 1;            // 0..255
    const int aq   = (tid & 1) * 4;       // 0 or 4
    const int brow = tid >> 2;            // 0..127
    const int bq   = (tid & 3) * 2;       // 0,2,4,6

    auto load_buf = [&](int buf, int c) {
        const uint32_t Ao = sbase + buf * STAGE_B;
        const uint32_t Bo = Ao + A_TILE_B;
        const size_t An = (size_t)arow * NN + (size_t)c * 64;
        const size_t Bn = (size_t)brow * NN + (size_t)c * 64;
#pragma unroll
        for (int i = 0; i < 4; ++i) {
            int ch = aq + i;
            uint32_t sw = (uint32_t)(ch ^ (arow & 7)) * 16 + (uint32_t)arow * 128;
            cp_async16(Ao + sw, Ag + (An + ch * 8) * 2);
        }
#pragma unroll
        for (int i = 0; i < 2; ++i) {
            int ch = bq + i;
            uint32_t sw = (uint32_t)(ch ^ (brow & 7)) * 16 + (uint32_t)brow * 128;
            cp_async16(Bo + sw, Bg + (Bn + ch * 8) * 2);
        }
        cp_commit();
    };

    float acc[4][4][4];
#pragma unroll
    for (int mf = 0; mf < 4; ++mf)
#pragma unroll
        for (int nf = 0; nf < 4; ++nf)
#pragma unroll
            for (int e = 0; e < 4; ++e) acc[mf][nf][e] = 0.f;

    load_buf(0, 0);
    load_buf(1, 1);
    load_buf(2, 2);

    // rinv for this CTA's 256 m-rows (same summation order as before)
    if (tid < 256) {
        float s = 0.f;
#pragma unroll
        for (int c = 0; c < TCHUNKS; ++c)
            s += g_part[c * NN + m0 + tid];
        rinv_s[tid] = rsqrtf(s);
    }

    const int portion = lane >> 3;
    const int w8 = lane & 7;

    for (int c = 0; c < NCHUNKS; ++c) {
        if (c + 2 < NCHUNKS)      cp_wait<2>();
        else if (c + 1 < NCHUNKS) cp_wait<1>();
        else                      cp_wait<0>();
        __syncthreads();
        if (c + 3 < NCHUNKS) load_buf((c + 3) & 3, c + 3);

        const uint32_t Ao = sbase + (c & 3) * STAGE_B;
        const uint32_t Bo = Ao + A_TILE_B;

#pragma unroll
        for (int ks = 0; ks < 4; ++ks) {
            const int kb8 = ks * 2;
            uint32_t a[4][4], b[4][2];
#pragma unroll
            for (int mf = 0; mf < 4; ++mf) {
                int row = warp_m + mf * 16 + (portion & 1) * 8 + w8;
                int ch  = kb8 + (portion >> 1);
                ldsm_x4(a[mf], Ao + (uint32_t)row * 128 + (uint32_t)(ch ^ (row & 7)) * 16);
            }
#pragma unroll
            for (int nfp = 0; nfp < 2; ++nfp) {
                int row = warp_d + nfp * 16 + (portion >> 1) * 8 + w8;
                int ch  = kb8 + (portion & 1);
                uint32_t r[4];
                ldsm_x4(r, Bo + (uint32_t)row * 128 + (uint32_t)(ch ^ (row & 7)) * 16);
                b[2 * nfp][0]     = r[0];
                b[2 * nfp][1]     = r[1];
                b[2 * nfp + 1][0] = r[2];
                b[2 * nfp + 1][1] = r[3];
            }
#pragma unroll
            for (int mf = 0; mf < 4; ++mf)
#pragma unroll
                for (int nf = 0; nf < 4; ++nf)
                    mma16816(acc[mf][nf], a[mf], b[nf]);
        }
    }

    const int g  = lane >> 2;
    const int tc = lane & 3;
    float* outab = out + (size_t)ab * NN * DOUT;
#pragma unroll
    for (int mf = 0; mf < 4; ++mf) {
        const int ml = warp_m + mf * 16 + g;        // local m
        const int mrow0 = m0 + ml;
        const float rv0 = rinv_s[ml];
        const float rv1 = rinv_s[ml + 8];
#pragma unroll
        for (int nf = 0; nf < 4; ++nf) {
            const int d0 = warp_d + nf * 8 + tc * 2;
            const float b0 = __ldg(&bias[d0]);
            const float b1 = __ldg(&bias[d0 + 1]);
            float2 v0, v1;
            v0.x = fmaxf(fmaf(acc[mf][nf][0], rv0, b0), 0.f);
            v0.y = fmaxf(fmaf(acc[mf][nf][1], rv0, b1), 0.f);
            v1.x = fmaxf(fmaf(acc[mf][nf][2], rv1, b0), 0.f);
            v1.y = fmaxf(fmaf(acc[mf][nf][3], rv1, b1), 0.f);
            *(float2*)&outab[(size_t)mrow0 * DOUT + d0]       = v0;
            *(float2*)&outab[(size_t)(mrow0 + 8) * DOUT + d0] = v1;
        }
    }
}

// ============================================================
extern "C" void kernel_launch(void* const* d_in, const int* in_sizes, int n_in,
                              void* d_out, int out_size) {
    const float* adj  = (const float*)d_in[0];
    const float* x    = (const float*)d_in[1];
    const float* w    = (const float*)d_in[2];
    const float* bias = (const float*)d_in[3];
    float* out        = (float*)d_out;

    const int agg_smem  = NSTAGES * STAGE_B + 256;   // 192 KB + slack
    const int proj_smem = 4 * PTILE_B + 256;         // 64 KB + slack
    cudaFuncSetAttribute(aggregate_mma, cudaFuncAttributeMaxDynamicSharedMemorySize, agg_smem);
    cudaFuncSetAttribute(project_mma, cudaFuncAttributeMaxDynamicSharedMemorySize, proj_smem);

    transpose_colsum_kernel<<<dim3(16, 33), 256>>>(adj, w);
    project_mma<<<dim3(16, 16), 512, proj_smem>>>(x);
    aggregate_mma<<<dim3(8, 16), 512, agg_smem>>>(bias, out);
}

// round 16
// speedup vs baseline: 1.4145x; 1.1882x over previous
#include <cuda_runtime.h>
#include <cuda_bf16.h>
#include <cstdint>

// dims fixed by setup_inputs
#define NN     2048
#define ABATCH 16
#define DIN    128
#define DOUT   128
#define TCHUNKS 32

// ---------------- device scratch (no allocs allowed) ----------------
__device__ float g_part[TCHUNKS * NN];
__device__ __nv_bfloat16 g_adjb[(size_t)NN * NN];           // bf16(adj), native [n][m], 8 MB
__device__ __nv_bfloat16 g_yT[(size_t)ABATCH * DOUT * NN];  // yT[ab][d][n], 8 MB
__device__ __nv_bfloat16 g_wt[DOUT * DIN];                  // WT[d][k] bf16

__device__ __forceinline__ uint32_t smem_u32(const void* p) {
    return (uint32_t)__cvta_generic_to_shared(p);
}
__device__ __forceinline__ void cp_async16(uint32_t dst, const void* src) {
    asm volatile("cp.async.cg.shared.global [%0], [%1], 16;" :: "r"(dst), "l"(src));
}
__device__ __forceinline__ void cp_commit() {
    asm volatile("cp.async.commit_group;" ::: "memory");
}
template <int N>
__device__ __forceinline__ void cp_wait() {
    asm volatile("cp.async.wait_group %0;" :: "n"(N) : "memory");
}
__device__ __forceinline__ void ldsm_x4(uint32_t* r, uint32_t addr) {
    asm volatile("ldmatrix.sync.aligned.m8n8.x4.shared.b16 {%0,%1,%2,%3}, [%4];"
                 : "=r"(r[0]), "=r"(r[1]), "=r"(r[2]), "=r"(r[3]) : "r"(addr));
}
__device__ __forceinline__ void ldsm_x4_trans(uint32_t* r, uint32_t addr) {
    asm volatile("ldmatrix.sync.aligned.m8n8.x4.trans.shared.b16 {%0,%1,%2,%3}, [%4];"
                 : "=r"(r[0]), "=r"(r[1]), "=r"(r[2]), "=r"(r[3]) : "r"(addr));
}
__device__ __forceinline__ void mma16816(float* d, const uint32_t* a, const uint32_t* b) {
    asm volatile(
        "mma.sync.aligned.m16n8k16.row.col.f32.bf16.bf16.f32 "
        "{%0,%1,%2,%3}, {%4,%5,%6,%7}, {%8,%9}, {%0,%1,%2,%3};"
        : "+f"(d[0]), "+f"(d[1]), "+f"(d[2]), "+f"(d[3])
        : "r"(a[0]), "r"(a[1]), "r"(a[2]), "r"(a[3]), "r"(b[0]), "r"(b[1]));
}
__device__ __forceinline__ uint32_t pack_bf2(float a, float b) {
    __nv_bfloat162 t = __floats2bfloat162_rn(a, b);
    return *(uint32_t*)&t;
}

// ============================================================
// Kernel 1: streaming convert + partial column sums (NO transpose)
//   g_adjb[n][m] = bf16(adj[n][m]);  g_part[strip][m] = sum_{n in strip} adj[n][m]
//   + WT build (grid row y=32, blocks x<8)
// grid (8, 33), 256 threads; each block: 256 cols x 64 rows, 1 col/thread.
// ============================================================
__global__ void __launch_bounds__(256) conv_colsum_kernel(const float* __restrict__ adj,
                                                          const float* __restrict__ w) {
    if (blockIdx.y == 32) {
        if (blockIdx.x >= 8) return;
        int idx = (blockIdx.x * 256 + threadIdx.x) * 8;
        int d  = idx >> 7;
        int k0 = idx & 127;
        uint4 pk;
        float a0 = w[(size_t)(k0 + 0) * DOUT + d], a1 = w[(size_t)(k0 + 1) * DOUT + d];
        float a2 = w[(size_t)(k0 + 2) * DOUT + d], a3 = w[(size_t)(k0 + 3) * DOUT + d];
        float a4 = w[(size_t)(k0 + 4) * DOUT + d], a5 = w[(size_t)(k0 + 5) * DOUT + d];
        float a6 = w[(size_t)(k0 + 6) * DOUT + d], a7 = w[(size_t)(k0 + 7) * DOUT + d];
        pk.x = pack_bf2(a0, a1);
        pk.y = pack_bf2(a2, a3);
        pk.z = pack_bf2(a4, a5);
        pk.w = pack_bf2(a6, a7);
        *(uint4*)((char*)g_wt + (size_t)idx * 2) = pk;
        return;
    }

    const int col = blockIdx.x * 256 + threadIdx.x;
    const int r0  = blockIdx.y * 64;
    float s = 0.f;
#pragma unroll 8
    for (int r = 0; r < 64; ++r) {
        float v = adj[(size_t)(r0 + r) * NN + col];
        s += v;
        g_adjb[(size_t)(r0 + r) * NN + col] = __float2bfloat16(v);
    }
    g_part[blockIdx.y * NN + col] = s;
}

// ============================================================
// Kernel 2: fused convert+projection via mma.sync; rinv computed in-kernel
//   yT[ab][d][n] = bf16( rinv[n] * sum_k WT[d][k] * bf16(x[ab][n][k]) )
// CTA: 128d x 128n, 512 threads, 16 warps (4d x 4n), warp tile 32x32.
// grid (16 n-tiles, 16 ab).
// ============================================================
#define PTILE_B (128 * 128)   // one 64-k chunk tile: 128 rows x 128B = 16 KB

__global__ void __launch_bounds__(512, 1)
project_mma(const float* __restrict__ x) {
    extern __shared__ char smem_raw[];
    __shared__ float rinv_s[128];
    const uint32_t sbase = (smem_u32(smem_raw) + 127) & ~127u;
    const uint32_t Ao0 = sbase;                  // WT chunks: 2 x 16KB
    const uint32_t Bo0 = sbase + 2 * PTILE_B;    // x-bf16 chunks: 2 x 16KB

    const int tid  = threadIdx.x;
    const int wid  = tid >> 5;
    const int lane = tid & 31;
    const int warp_m = (wid & 3) * 32;     // d
    const int warp_d = (wid >> 2) * 32;    // n (local)
    const int n0 = blockIdx.x * 128;
    const int ab = blockIdx.y;

    // WT via cp.async into swizzled A tiles
    {
        const char* Ag = (const char*)g_wt;
        const int lrow = tid >> 2;
        const int lc0  = (tid & 3) * 2;
#pragma unroll
        for (int c = 0; c < 2; ++c)
#pragma unroll
            for (int i = 0; i < 2; ++i) {
                int ch = lc0 + i;
                uint32_t sw = (uint32_t)(ch ^ (lrow & 7)) * 16 + (uint32_t)lrow * 128;
                size_t goff = ((size_t)lrow * DIN + c * 64 + ch * 8) * 2;
                cp_async16(Ao0 + c * PTILE_B + sw, Ag + goff);
            }
        cp_commit();
    }

    // x fp32 -> bf16 swizzled B tiles, in registers
    {
        const float* xab = x + ((size_t)ab * NN + n0) * DIN;
        const int f4c = tid & 31;
        const int chunk = f4c >> 4;
        const int ku    = (f4c & 15) >> 1;
        const int half  = f4c & 1;
#pragma unroll
        for (int i = 0; i < 8; ++i) {
            const int row = (tid >> 5) + i * 16;
            float4 v = *(const float4*)&xab[(size_t)row * DIN + f4c * 4];
            uint32_t lo = pack_bf2(v.x, v.y);
            uint32_t hi = pack_bf2(v.z, v.w);
            uint32_t addr = Bo0 + chunk * PTILE_B + (uint32_t)row * 128
                          + (uint32_t)(ku ^ (row & 7)) * 16 + half * 8;
            asm volatile("st.shared.v2.b32 [%0], {%1, %2};" :: "r"(addr), "r"(lo), "r"(hi));
        }
    }

    // rinv for this CTA's 128 n-columns
    if (tid < 128) {
        float s = 0.f;
#pragma unroll
        for (int c = 0; c < TCHUNKS; ++c)
            s += g_part[c * NN + n0 + tid];
        rinv_s[tid] = rsqrtf(s);
    }

    cp_wait<0>();
    __syncthreads();

    float acc[2][4][4];
#pragma unroll
    for (int mf = 0; mf < 2; ++mf)
#pragma unroll
        for (int nf = 0; nf < 4; ++nf)
#pragma unroll
            for (int e = 0; e < 4; ++e) acc[mf][nf][e] = 0.f;

    const int portion = lane >> 3;
    const int w8 = lane & 7;

#pragma unroll
    for (int c = 0; c < 2; ++c) {
        const uint32_t Ao = Ao0 + c * PTILE_B;
        const uint32_t Bo = Bo0 + c * PTILE_B;
#pragma unroll
        for (int ks = 0; ks < 4; ++ks) {
            const int kb8 = ks * 2;
            uint32_t a[2][4], b[4][2];
#pragma unroll
            for (int mf = 0; mf < 2; ++mf) {
                int row = warp_m + mf * 16 + (portion & 1) * 8 + w8;
                int ch  = kb8 + (portion >> 1);
                ldsm_x4(a[mf], Ao + (uint32_t)row * 128 + (uint32_t)(ch ^ (row & 7)) * 16);
            }
#pragma unroll
            for (int nfp = 0; nfp < 2; ++nfp) {
                int row = warp_d + nfp * 16 + (portion >> 1) * 8 + w8;
                int ch  = kb8 + (portion & 1);
                uint32_t r[4];
                ldsm_x4(r, Bo + (uint32_t)row * 128 + (uint32_t)(ch ^ (row & 7)) * 16);
                b[2 * nfp][0]     = r[0];
                b[2 * nfp][1]     = r[1];
                b[2 * nfp + 1][0] = r[2];
                b[2 * nfp + 1][1] = r[3];
            }
#pragma unroll
            for (int mf = 0; mf < 2; ++mf)
#pragma unroll
                for (int nf = 0; nf < 4; ++nf)
                    mma16816(acc[mf][nf], a[mf], b[nf]);
        }
    }

    const int g  = lane >> 2;
    const int tc = lane & 3;
    char* yT = (char*)(g_yT + (size_t)ab * DOUT * NN);
#pragma unroll
    for (int mf = 0; mf < 2; ++mf) {
        const int d0g = warp_m + mf * 16 + g;
#pragma unroll
        for (int nf = 0; nf < 4; ++nf) {
            const int nl = warp_d + nf * 8 + tc * 2;     // local n
            const int ng = n0 + nl;
            const float rv0 = rinv_s[nl];
            const float rv1 = rinv_s[nl + 1];
            *(uint32_t*)(yT + ((size_t)d0g * NN + ng) * 2) =
                pack_bf2(acc[mf][nf][0] * rv0, acc[mf][nf][1] * rv1);
            *(uint32_t*)(yT + ((size_t)(d0g + 8) * NN + ng) * 2) =
                pack_bf2(acc[mf][nf][2] * rv0, acc[mf][nf][3] * rv1);
        }
    }
}

// ============================================================
// Kernel 3: mma.sync bf16 aggregate, A consumed via ldmatrix.trans
//   out[ab][m][d] = relu( rinv[m] * sum_n adj[n][m]*yT[ab][d][n] + bias[d] )
// 512 threads, 16 warps (4m x 4d), warp tile 64m x 32d. BK=64.
// A tile: stored [64 n][256 m] bf16 = 64 rows x 512B (32 KB), swizzled per
// 128B segment. B tile: yT [128 d][64 n] (16 KB), unchanged. 4 stages.
// grid (8 m-tiles, 16 ab) = 128 CTAs = one wave.
// ============================================================
#define A_TILE_B  (64 * 512)           // 32 KB
#define B_TILE_B  (128 * 128)          // 16 KB
#define STAGE_B   (A_TILE_B + B_TILE_B) // 48 KB
#define NSTAGES   4
#define NCHUNKS   32                   // 2048 / 64

__global__ void __launch_bounds__(512, 1)
aggregate_mma(const float* __restrict__ bias, float* __restrict__ out) {
    extern __shared__ char smem_raw[];
    __shared__ float rinv_s[256];
    const uint32_t sbase = (smem_u32(smem_raw) + 127) & ~127u;

    const int tid  = threadIdx.x;
    const int wid  = tid >> 5;
    const int lane = tid & 31;
    const int warp_m = (wid & 3) * 64;     // 0,64,128,192
    const int warp_d = (wid >> 2) * 32;    // 0,32,64,96
    const int m0   = blockIdx.x * 256;
    const int ab   = blockIdx.y;

    const char* Ag = (const char*)g_adjb;                       // [n][m]
    const char* Bg = (const char*)(g_yT + (size_t)ab * DOUT * NN);

    // A loader: 64 rows x 32 f4 = 2048 f4 -> 4/thread
    const int arow = tid >> 3;            // 0..63 (n within chunk)
    const int af0  = tid & 7;             // f4 base
    // B loader: 128 rows x 8 f4 = 1024 f4 -> 2/thread
    const int brow = tid >> 2;            // 0..127
    const int bq   = (tid & 3) * 2;       // 0,2,4,6

    auto load_buf = [&](int buf, int c) {
        const uint32_t Ao = sbase + buf * STAGE_B;
        const uint32_t Bo = Ao + A_TILE_B;
        const size_t An = (size_t)(c * 64 + arow) * NN + m0;
        const size_t Bn = (size_t)brow * NN + (size_t)c * 64;
#pragma unroll
        for (int i = 0; i < 4; ++i) {
            int f4c = af0 + i * 8;        // 0..31
            int seg = f4c >> 3;
            int ku  = f4c & 7;
            uint32_t sw = (uint32_t)arow * 512 + (uint32_t)seg * 128
                        + (uint32_t)(ku ^ (arow & 7)) * 16;
            cp_async16(Ao + sw, Ag + (An + f4c * 8) * 2);
        }
#pragma unroll
        for (int i = 0; i < 2; ++i) {
            int ch = bq + i;
            uint32_t sw = (uint32_t)(ch ^ (brow & 7)) * 16 + (uint32_t)brow * 128;
            cp_async16(Bo + sw, Bg + (Bn + ch * 8) * 2);
        }
        cp_commit();
    };

    float acc[4][4][4];
#pragma unroll
    for (int mf = 0; mf < 4; ++mf)
#pragma unroll
        for (int nf = 0; nf < 4; ++nf)
#pragma unroll
            for (int e = 0; e < 4; ++e) acc[mf][nf][e] = 0.f;

    load_buf(0, 0);
    load_buf(1, 1);
    load_buf(2, 2);

    // rinv for this CTA's 256 m-rows
    if (tid < 256) {
        float s = 0.f;
#pragma unroll
        for (int c = 0; c < TCHUNKS; ++c)
            s += g_part[c * NN + m0 + tid];
        rinv_s[tid] = rsqrtf(s);
    }

    const int portion = lane >> 3;
    const int w8 = lane & 7;

    for (int c = 0; c < NCHUNKS; ++c) {
        if (c + 2 < NCHUNKS)      cp_wait<2>();
        else if (c + 1 < NCHUNKS) cp_wait<1>();
        else                      cp_wait<0>();
        __syncthreads();
        if (c + 3 < NCHUNKS) load_buf((c + 3) & 3, c + 3);

        const uint32_t Ao = sbase + (c & 3) * STAGE_B;
        const uint32_t Bo = Ao + A_TILE_B;

#pragma unroll
        for (int ks = 0; ks < 4; ++ks) {
            const int kb8 = ks * 2;
            uint32_t a[4][4], b[4][2];
            // A via ldmatrix.trans: stored row = n (k of GEMM), column = m.
            // portion&1 -> m-half (8 m's), portion>>1 -> k-half (8 n's).
#pragma unroll
            for (int mf = 0; mf < 4; ++mf) {
                int srow = ks * 16 + (portion >> 1) * 8 + w8;        // n within 64
                int mb   = (warp_m + mf * 16 + (portion & 1) * 8) * 2;  // byte col
                int seg  = mb >> 7;
                int ku   = (mb & 127) >> 4;
                ldsm_x4_trans(a[mf], Ao + (uint32_t)srow * 512 + (uint32_t)seg * 128
                                        + (uint32_t)(ku ^ (srow & 7)) * 16);
            }
#pragma unroll
            for (int nfp = 0; nfp < 2; ++nfp) {
                int row = warp_d + nfp * 16 + (portion >> 1) * 8 + w8;
                int ch  = kb8 + (portion & 1);
                uint32_t r[4];
                ldsm_x4(r, Bo + (uint32_t)row * 128 + (uint32_t)(ch ^ (row & 7)) * 16);
                b[2 * nfp][0]     = r[0];
                b[2 * nfp][1]     = r[1];
                b[2 * nfp + 1][0] = r[2];
                b[2 * nfp + 1][1] = r[3];
            }
#pragma unroll
            for (int mf = 0; mf < 4; ++mf)
#pragma unroll
                for (int nf = 0; nf < 4; ++nf)
                    mma16816(acc[mf][nf], a[mf], b[nf]);
        }
    }

    const int g  = lane >> 2;
    const int tc = lane & 3;
    float* outab = out + (size_t)ab * NN * DOUT;
#pragma unroll
    for (int mf = 0; mf < 4; ++mf) {
        const int ml = warp_m + mf * 16 + g;        // local m
        const int mrow0 = m0 + ml;
        const float rv0 = rinv_s[ml];
        const float rv1 = rinv_s[ml + 8];
#pragma unroll
        for (int nf = 0; nf < 4; ++nf) {
            const int d0 = warp_d + nf * 8 + tc * 2;
            const float b0 = __ldg(&bias[d0]);
            const float b1 = __ldg(&bias[d0 + 1]);
            float2 v0, v1;
            v0.x = fmaxf(fmaf(acc[mf][nf][0], rv0, b0), 0.f);
            v0.y = fmaxf(fmaf(acc[mf][nf][1], rv0, b1), 0.f);
            v1.x = fmaxf(fmaf(acc[mf][nf][2], rv1, b0), 0.f);
            v1.y = fmaxf(fmaf(acc[mf][nf][3], rv1, b1), 0.f);
            *(float2*)&outab[(size_t)mrow0 * DOUT + d0]       = v0;
            *(float2*)&outab[(size_t)(mrow0 + 8) * DOUT + d0] = v1;
        }
    }
}

// ============================================================
extern "C" void kernel_launch(void* const* d_in, const int* in_sizes, int n_in,
                              void* d_out, int out_size) {
    const float* adj  = (const float*)d_in[0];
    const float* x    = (const float*)d_in[1];
    const float* w    = (const float*)d_in[2];
    const float* bias = (const float*)d_in[3];
    float* out        = (float*)d_out;

    const int agg_smem  = NSTAGES * STAGE_B + 256;   // 192 KB + slack
    const int proj_smem = 4 * PTILE_B + 256;         // 64 KB + slack
    cudaFuncSetAttribute(aggregate_mma, cudaFuncAttributeMaxDynamicSharedMemorySize, agg_smem);
    cudaFuncSetAttribute(project_mma, cudaFuncAttributeMaxDynamicSharedMemorySize, proj_smem);

    conv_colsum_kernel<<<dim3(8, 33), 256>>>(adj, w);
    project_mma<<<dim3(16, 16), 512, proj_smem>>>(x);
    aggregate_mma<<<dim3(8, 16), 512, agg_smem>>>(bias, out);
}